// round 6
// baseline (speedup 1.0000x reference)
#include <cuda_runtime.h>
#include <cuda_fp16.h>
#include <cstdint>

#define B_ 2
#define L_ 512
#define V_ 64
#define D_ 128
#define NC_ 8

// ---- static device scratch (no allocations allowed) ----
__device__ float g_sumK[B_ * L_ * D_];
__device__ int   g_idx[B_][NC_][L_];
__device__ int   g_cnt[B_][NC_];

// ===========================================================================
// Kernel 1: sumK[b,l,d] = sum_v key[b,l,v,d]  (256 thr, v split 8-way)
// ===========================================================================
__global__ void sumk_kernel(const float4* __restrict__ key4) {
    __shared__ float4 part[256];
    int bl = blockIdx.x;
    int g = threadIdx.x & 31, q = threadIdx.x >> 5;
    const float4* p = key4 + (size_t)bl * (V_ * D_ / 4) + (size_t)(q * 8) * (D_ / 4) + g;
    float4 s = make_float4(0.f, 0.f, 0.f, 0.f);
#pragma unroll
    for (int v = 0; v < 8; v++) {
        float4 t = p[(size_t)v * (D_ / 4)];
        s.x += t.x; s.y += t.y; s.z += t.z; s.w += t.w;
    }
    part[threadIdx.x] = s;
    __syncthreads();
    if (q < 4) {
        float4 a = part[threadIdx.x], b2 = part[threadIdx.x + 128];
        part[threadIdx.x] = make_float4(a.x + b2.x, a.y + b2.y, a.z + b2.z, a.w + b2.w);
    }
    __syncthreads();
    if (q == 0) {
        float4 a = part[g], b2 = part[32 + g], c2 = part[64 + g], d2 = part[96 + g];
        ((float4*)g_sumK)[(size_t)bl * 32 + g] =
            make_float4(a.x + b2.x + c2.x + d2.x, a.y + b2.y + c2.y + d2.y,
                        a.z + b2.z + c2.z + d2.z, a.w + b2.w + c2.w + d2.w);
    }
}

// ===========================================================================
// Kernel 2: deterministic per-(b,c) index lists via ballot compaction
// ===========================================================================
__global__ void build_idx_kernel(const int* __restrict__ label) {
    int c = blockIdx.x, b = blockIdx.y;
    int lane = threadIdx.x;
    int cnt = 0;
    for (int l0 = 0; l0 < L_; l0 += 32) {
        int l = l0 + lane;
        int lbl = label[b * L_ + l];
        unsigned m = __ballot_sync(0xffffffffu, lbl == c);
        if (lbl == c) {
            int pos = cnt + __popc(m & ((1u << lane) - 1u));
            g_idx[b][c][pos] = l;
        }
        cnt += __popc(m);
    }
    if (lane == 0) g_cnt[b][c] = cnt;
}

// ===========================================================================
// mma.sync / ldmatrix helpers (family-common PTX, valid on target sm_103)
// ===========================================================================
__device__ __forceinline__ uint32_t smem_u32(const void* p) {
    uint32_t a;
    asm("{ .reg .u64 t; cvta.to.shared.u64 t, %1; cvt.u32.u64 %0, t; }"
        : "=r"(a) : "l"(p));
    return a;
}
__device__ __forceinline__ void ldsm4(uint32_t addr, uint32_t* r) {
    asm volatile("ldmatrix.sync.aligned.m8n8.x4.shared.b16 {%0,%1,%2,%3}, [%4];"
                 : "=r"(r[0]), "=r"(r[1]), "=r"(r[2]), "=r"(r[3]) : "r"(addr));
}
__device__ __forceinline__ void ldsm4t(uint32_t addr, uint32_t* r) {
    asm volatile("ldmatrix.sync.aligned.m8n8.x4.trans.shared.b16 {%0,%1,%2,%3}, [%4];"
                 : "=r"(r[0]), "=r"(r[1]), "=r"(r[2]), "=r"(r[3]) : "r"(addr));
}
__device__ __forceinline__ void mma16816(float* c, const uint32_t* a,
                                         uint32_t b0, uint32_t b1) {
    asm volatile(
        "mma.sync.aligned.m16n8k16.row.col.f32.f16.f16.f32 "
        "{%0,%1,%2,%3}, {%4,%5,%6,%7}, {%8,%9}, {%0,%1,%2,%3};"
        : "+f"(c[0]), "+f"(c[1]), "+f"(c[2]), "+f"(c[3])
        : "r"(a[0]), "r"(a[1]), "r"(a[2]), "r"(a[3]), "r"(b0), "r"(b1));
}
// fp16 split: x = hi + lo; hi*hi exact in fp32, dropped lo*lo ~2^-22 rel
__device__ __forceinline__ void split2(float x0, float x1,
                                       uint32_t& hi, uint32_t& lo) {
    __half h0 = __float2half_rn(x0), h1 = __float2half_rn(x1);
    __half l0 = __float2half_rn(x0 - __half2float(h0));
    __half l1 = __float2half_rn(x1 - __half2float(h1));
    __half2 hp = __halves2half2(h0, h1), lp = __halves2half2(l0, l1);
    hi = *reinterpret_cast<uint32_t*>(&hp);
    lo = *reinterpret_cast<uint32_t*>(&lp);
}
// byte offset in a 128x128 f16 tile, 256B rows, 16B-chunk XOR swizzle
__device__ __forceinline__ uint32_t swz(int row, int col) {
    return (uint32_t)(row * 256) + (uint32_t)((((col >> 3) ^ (row & 7)) & 15) << 4)
         + (uint32_t)((col & 7) << 1);
}

// smem layout (bytes); Q tiles are reused as P tiles after softmax
#define SM_PHI  0
#define SM_PLO  32768
#define SM_KHI  65536
#define SM_KLO  98304
#define SM_VHI  131072
#define SM_VLO  163840
#define SM_IDX  196608
#define SM_RED  198656   /* redm[2][128], redl[2][128] */
#define SMEM_TOTAL 200704

// Dead-code-in-practice fallback for nc > 128 (slow, simple, correct).
__device__ __noinline__ void attn_fallback(int b, int c, int k, int nc,
                                           const int* idxs,
                                           const float* query,
                                           const float* value,
                                           float* out) {
    const float scale = 0.08838834764831845f;
    for (int r = threadIdx.x; r < nc; r += blockDim.x) {
        int i = idxs[r];
        const float* q = query + (((size_t)b * L_ + i) * V_ + k) * D_;
        float m = -1e30f;
        for (int jj = 0; jj < nc; jj++) {
            const float* kr = g_sumK + ((size_t)b * L_ + idxs[jj]) * D_;
            float s = 0.f;
            for (int d = 0; d < D_; d++) s += q[d] * kr[d];
            m = fmaxf(m, s * scale);
        }
        float l = 0.f;
        for (int jj = 0; jj < nc; jj++) {
            const float* kr = g_sumK + ((size_t)b * L_ + idxs[jj]) * D_;
            float s = 0.f;
            for (int d = 0; d < D_; d++) s += q[d] * kr[d];
            l += __expf(s * scale - m);
        }
        for (int d0 = 0; d0 < D_; d0 += 32) {
            float acc[32];
            for (int e = 0; e < 32; e++) acc[e] = 0.f;
            for (int jj = 0; jj < nc; jj++) {
                const float* kr = g_sumK + ((size_t)b * L_ + idxs[jj]) * D_;
                float s = 0.f;
                for (int d = 0; d < D_; d++) s += q[d] * kr[d];
                float p = __expf(s * scale - m) / l;
                const float* vr = value +
                    (((size_t)b * L_ + idxs[jj]) * V_ + k) * D_ + d0;
                for (int e = 0; e < 32; e++) acc[e] += p * vr[e];
            }
            float* dst = out + (((size_t)b * L_ + i) * V_ + k) * D_ + d0;
            for (int e = 0; e < 32; e++) dst[e] = acc[e];
        }
    }
}

// ===========================================================================
// Kernel 3: HMMA clustered attention. CTA = (head k, cluster c, batch b).
// 8 warps; warp pair (strip, half): strip = 16 rows, half splits n/d dims.
// ===========================================================================
extern __shared__ char smx[];

__global__ __launch_bounds__(256, 1)
void attn_mma_kernel(const float* __restrict__ query,
                     const float* __restrict__ value,
                     float* __restrict__ out) {
    const int k = blockIdx.x, c = blockIdx.y, b = blockIdx.z;
    const int tid = threadIdx.x;
    const int lane = tid & 31;
    const int w = tid >> 5;
    const int half = w & 1;        // n-tile / d-range parity
    const int pairid = w >> 1;     // 0..3 : strip within iteration
    const float scale = 0.08838834764831845f;

    const int nc = g_cnt[b][c];
    if (nc == 0) return;
    int* idxs = (int*)(smx + SM_IDX);
    for (int t = tid; t < nc; t += 256) idxs[t] = g_idx[b][c][t];
    __syncthreads();
    if (nc > 128) { attn_fallback(b, c, k, nc, idxs, query, value, out); return; }

    const int nr = (nc + 15) & ~15;
    const int npair = nr >> 4;            // number of 16-wide n / k tiles

    // ---- gather + fp16-split conversion into smem tiles ------------------
    for (int t = tid; t < nr * 64; t += 256) {     // 64 float2 per row
        int row = t >> 6, cp = t & 63;
        float2 x = make_float2(0.f, 0.f);
        if (row < nc)
            x = ((const float2*)query)[
                    ((((size_t)b * L_ + idxs[row]) * V_ + k) << 6) + cp];
        uint32_t hi, lo;
        split2(x.x * scale, x.y * scale, hi, lo);
        uint32_t off = swz(row, cp << 1);
        *(uint32_t*)(smx + SM_PHI + off) = hi;
        *(uint32_t*)(smx + SM_PLO + off) = lo;
    }
    for (int t = tid; t < nr * 64; t += 256) {
        int row = t >> 6, cp = t & 63;
        float2 x = make_float2(0.f, 0.f);
        if (row < nc)
            x = ((const float2*)g_sumK)[(((size_t)b * L_ + idxs[row]) << 6) + cp];
        uint32_t hi, lo;
        split2(x.x, x.y, hi, lo);
        uint32_t off = swz(row, cp << 1);
        *(uint32_t*)(smx + SM_KHI + off) = hi;
        *(uint32_t*)(smx + SM_KLO + off) = lo;
    }
    for (int t = tid; t < nr * 64; t += 256) {
        int row = t >> 6, cp = t & 63;
        float2 x = make_float2(0.f, 0.f);
        if (row < nc)
            x = ((const float2*)value)[
                    ((((size_t)b * L_ + idxs[row]) * V_ + k) << 6) + cp];
        uint32_t hi, lo;
        split2(x.x, x.y, hi, lo);
        uint32_t off = swz(row, cp << 1);
        *(uint32_t*)(smx + SM_VHI + off) = hi;
        *(uint32_t*)(smx + SM_VLO + off) = lo;
    }
    __syncthreads();

    const uint32_t sb  = smem_u32(smx);
    const uint32_t phi = sb + SM_PHI, plo = sb + SM_PLO;
    const uint32_t khi = sb + SM_KHI, klo = sb + SM_KLO;
    const uint32_t vhi = sb + SM_VHI, vlo = sb + SM_VLO;
    float* redm = (float*)(smx + SM_RED);      // [2][128]
    float* redl = redm + 256;

    const int g  = lane >> 3;
    const int rA = (lane & 7) + ((g & 1) << 3);        // A / V-trans rows
    const int cA = ((g >> 1) & 1) << 3;
    const int rB = (lane & 7) + (((g >> 1) & 1) << 3); // B (K) rows
    const int cB = (g & 1) << 3;
    const int colb = (lane & 3) << 1;
    const int qr = lane >> 2;                           // quad row

    const int niter = (nc + 63) >> 6;
    for (int it = 0; it < niter; it++) {
        const int row0 = (it * 4 + pairid) * 16;
        const bool active = row0 < nc;
        const int r1 = row0 + qr, r2 = r1 + 8;

        // ================= S = Q * Ksum^T (tiles half, half+2, ...) ========
        float cS[8][4];
#pragma unroll
        for (int n = 0; n < 8; n++)
#pragma unroll
            for (int r = 0; r < 4; r++) cS[n][r] = 0.f;

        if (active) {
#pragma unroll
            for (int s = 0; s < 8; s++) {
                uint32_t ah[4], al[4];
                ldsm4(phi + swz(row0 + rA, s * 16 + cA), ah);
                ldsm4(plo + swz(row0 + rA, s * 16 + cA), al);
#pragma unroll
                for (int u = 0; u < 4; u++) {
                    int ti = half + 2 * u;
                    if (ti < npair) {
                        uint32_t bh[4], bl[4];
                        ldsm4(khi + swz(16 * ti + rB, s * 16 + cB), bh);
                        ldsm4(klo + swz(16 * ti + rB, s * 16 + cB), bl);
                        mma16816(cS[2 * u],     ah, bh[0], bh[1]);
                        mma16816(cS[2 * u],     ah, bl[0], bl[1]);
                        mma16816(cS[2 * u],     al, bh[0], bh[1]);
                        mma16816(cS[2 * u + 1], ah, bh[2], bh[3]);
                        mma16816(cS[2 * u + 1], ah, bl[2], bl[3]);
                        mma16816(cS[2 * u + 1], al, bh[2], bh[3]);
                    }
                }
            }
        }

        // ================= softmax: partial max -> smem ====================
        float m0 = -1e30f, m1 = -1e30f;
        if (active) {
#pragma unroll
            for (int u = 0; u < 4; u++) {
                int ti = half + 2 * u;
                if (ti < npair) {
#pragma unroll
                    for (int sub = 0; sub < 2; sub++) {
                        int n = 2 * u + sub;
                        int c0 = ti * 16 + sub * 8 + colb;
                        if (c0 < nc)     { m0 = fmaxf(m0, cS[n][0]); m1 = fmaxf(m1, cS[n][2]); }
                        if (c0 + 1 < nc) { m0 = fmaxf(m0, cS[n][1]); m1 = fmaxf(m1, cS[n][3]); }
                    }
                }
            }
            m0 = fmaxf(m0, __shfl_xor_sync(0xffffffffu, m0, 1));
            m0 = fmaxf(m0, __shfl_xor_sync(0xffffffffu, m0, 2));
            m1 = fmaxf(m1, __shfl_xor_sync(0xffffffffu, m1, 1));
            m1 = fmaxf(m1, __shfl_xor_sync(0xffffffffu, m1, 2));
            if ((lane & 3) == 0) {
                redm[half * 128 + r1] = m0;
                redm[half * 128 + r2] = m1;
            }
        }
        __syncthreads();   // all warps past S (Q reads done) + partial max in

        // ============== exp, P -> smem (over Q tiles), partial l ===========
        if (active) {
            float mt0 = fmaxf(redm[r1], redm[128 + r1]);
            float mt1 = fmaxf(redm[r2], redm[128 + r2]);
            float l0 = 0.f, l1 = 0.f;
#pragma unroll
            for (int u = 0; u < 4; u++) {
                int ti = half + 2 * u;
                if (ti < npair) {
#pragma unroll
                    for (int sub = 0; sub < 2; sub++) {
                        int n = 2 * u + sub;
                        int c0 = ti * 16 + sub * 8 + colb;
                        float p0 = (c0     < nc) ? __expf(cS[n][0] - mt0) : 0.f;
                        float p1 = (c0 + 1 < nc) ? __expf(cS[n][1] - mt0) : 0.f;
                        float p2 = (c0     < nc) ? __expf(cS[n][2] - mt1) : 0.f;
                        float p3 = (c0 + 1 < nc) ? __expf(cS[n][3] - mt1) : 0.f;
                        l0 += p0 + p1; l1 += p2 + p3;
                        uint32_t hi, lo;
                        split2(p0, p1, hi, lo);
                        *(uint32_t*)((char*)smx + SM_PHI + swz(r1, c0)) = hi;
                        *(uint32_t*)((char*)smx + SM_PLO + swz(r1, c0)) = lo;
                        split2(p2, p3, hi, lo);
                        *(uint32_t*)((char*)smx + SM_PHI + swz(r2, c0)) = hi;
                        *(uint32_t*)((char*)smx + SM_PLO + swz(r2, c0)) = lo;
                    }
                }
            }
            l0 += __shfl_xor_sync(0xffffffffu, l0, 1);
            l0 += __shfl_xor_sync(0xffffffffu, l0, 2);
            l1 += __shfl_xor_sync(0xffffffffu, l1, 1);
            l1 += __shfl_xor_sync(0xffffffffu, l1, 2);
            if ((lane & 3) == 0) {
                redl[half * 128 + r1] = l0;
                redl[half * 128 + r2] = l1;
            }
        }
        __syncthreads();   // P tiles + partial l complete

        // ================= O = P * V  (d-range = half*64 .. +63) ===========
        if (active) {
            float o[8][4];
#pragma unroll
            for (int n = 0; n < 8; n++)
#pragma unroll
                for (int r = 0; r < 4; r++) o[n][r] = 0.f;

#pragma unroll
            for (int kt = 0; kt < 8; kt++) {
                if (kt < npair) {
                    uint32_t ph[4], pl[4];
                    ldsm4(phi + swz(row0 + rA, kt * 16 + cA), ph);
                    ldsm4(plo + swz(row0 + rA, kt * 16 + cA), pl);
#pragma unroll
                    for (int dq = 0; dq < 4; dq++) {
                        int dp = half * 4 + dq;
                        uint32_t vh[4], vl[4];
                        ldsm4t(vhi + swz(16 * kt + rA, 16 * dp + cA), vh);
                        ldsm4t(vlo + swz(16 * kt + rA, 16 * dp + cA), vl);
                        mma16816(o[2 * dq],     ph, vh[0], vh[1]);
                        mma16816(o[2 * dq],     ph, vl[0], vl[1]);
                        mma16816(o[2 * dq],     pl, vh[0], vh[1]);
                        mma16816(o[2 * dq + 1], ph, vh[2], vh[3]);
                        mma16816(o[2 * dq + 1], ph, vl[2], vl[3]);
                        mma16816(o[2 * dq + 1], pl, vh[2], vh[3]);
                    }
                }
            }

            // ---- epilogue
            float lt0 = redl[r1] + redl[128 + r1];
            float lt1 = redl[r2] + redl[128 + r2];
            float i0 = 1.f / lt0, i1 = 1.f / lt1;
            float* d1 = (r1 < nc)
                ? out + (((size_t)b * L_ + idxs[r1]) * V_ + k) * D_ : nullptr;
            float* d2 = (r2 < nc)
                ? out + (((size_t)b * L_ + idxs[r2]) * V_ + k) * D_ : nullptr;
#pragma unroll
            for (int n = 0; n < 8; n++) {
                int col = half * 64 + n * 8 + colb;
                if (d1) *(float2*)(d1 + col) = make_float2(o[n][0] * i0, o[n][1] * i0);
                if (d2) *(float2*)(d2 + col) = make_float2(o[n][2] * i1, o[n][3] * i1);
            }
        }
        if (it + 1 < niter) __syncthreads();   // P reads done before reuse
    }
}

extern "C" void kernel_launch(void* const* d_in, const int* in_sizes, int n_in,
                              void* d_out, int out_size) {
    (void)in_sizes; (void)n_in; (void)out_size;
    const float* query = (const float*)d_in[0];
    const float* key   = (const float*)d_in[1];
    const float* value = (const float*)d_in[2];
    const int*   label = (const int*)d_in[3];
    float* out = (float*)d_out;

    sumk_kernel<<<B_ * L_, 256>>>((const float4*)key);
    build_idx_kernel<<<dim3(NC_, B_), 32>>>(label);
    cudaFuncSetAttribute(attn_mma_kernel,
                         cudaFuncAttributeMaxDynamicSharedMemorySize, SMEM_TOTAL);
    attn_mma_kernel<<<dim3(V_, NC_, B_), 256, SMEM_TOTAL>>>(query, value, out);
}

// round 7
// speedup vs baseline: 1.2890x; 1.2890x over previous
#include <cuda_runtime.h>
#include <cuda_fp16.h>
#include <cstdint>

#define B_ 2
#define L_ 512
#define V_ 64
#define D_ 128
#define NC_ 8
#define NR_MAX 96

// ---- static device scratch (no allocations allowed) ----
__device__ float  g_sumK[B_ * L_ * D_];
__device__ __half g_sKh[B_ * L_ * D_];
__device__ __half g_sKl[B_ * L_ * D_];
__device__ int    g_idx[B_][NC_][L_];
__device__ int    g_cnt[B_][NC_];
__device__ int    g_pad;

// ===========================================================================
// Kernel 0: 1-block pad kernel so ncu's fixed -s 5 lands on attn
// ===========================================================================
__global__ void prof_pad_kernel() { if (threadIdx.x == 0) g_pad = 1; }

// ===========================================================================
// Kernel 1: sumK = sum_v key; also emit fp16 hi/lo split of sumK
// ===========================================================================
__global__ void sumk_kernel(const float4* __restrict__ key4) {
    __shared__ float4 part[256];
    int bl = blockIdx.x;
    int g = threadIdx.x & 31, q = threadIdx.x >> 5;
    const float4* p = key4 + (size_t)bl * (V_ * D_ / 4) + (size_t)(q * 8) * (D_ / 4) + g;
    float4 s = make_float4(0.f, 0.f, 0.f, 0.f);
#pragma unroll
    for (int v = 0; v < 8; v++) {
        float4 t = p[(size_t)v * (D_ / 4)];
        s.x += t.x; s.y += t.y; s.z += t.z; s.w += t.w;
    }
    part[threadIdx.x] = s;
    __syncthreads();
    if (q < 4) {
        float4 a = part[threadIdx.x], b2 = part[threadIdx.x + 128];
        part[threadIdx.x] = make_float4(a.x + b2.x, a.y + b2.y, a.z + b2.z, a.w + b2.w);
    }
    __syncthreads();
    if (q == 0) {
        float4 a = part[g], b2 = part[32 + g], c2 = part[64 + g], d2 = part[96 + g];
        float4 r = make_float4(a.x + b2.x + c2.x + d2.x, a.y + b2.y + c2.y + d2.y,
                               a.z + b2.z + c2.z + d2.z, a.w + b2.w + c2.w + d2.w);
        ((float4*)g_sumK)[(size_t)bl * 32 + g] = r;
        __half hx = __float2half_rn(r.x), hy = __float2half_rn(r.y);
        __half hz = __float2half_rn(r.z), hw = __float2half_rn(r.w);
        __half lx = __float2half_rn(r.x - __half2float(hx));
        __half ly = __float2half_rn(r.y - __half2float(hy));
        __half lz = __float2half_rn(r.z - __half2float(hz));
        __half lw = __float2half_rn(r.w - __half2float(hw));
        size_t o = (size_t)bl * 64 + g * 2;
        ((__half2*)g_sKh)[o]     = __halves2half2(hx, hy);
        ((__half2*)g_sKh)[o + 1] = __halves2half2(hz, hw);
        ((__half2*)g_sKl)[o]     = __halves2half2(lx, ly);
        ((__half2*)g_sKl)[o + 1] = __halves2half2(lz, lw);
    }
}

// ===========================================================================
// Kernel 2: deterministic per-(b,c) index lists via ballot compaction
// ===========================================================================
__global__ void build_idx_kernel(const int* __restrict__ label) {
    int c = blockIdx.x, b = blockIdx.y;
    int lane = threadIdx.x;
    int cnt = 0;
    for (int l0 = 0; l0 < L_; l0 += 32) {
        int l = l0 + lane;
        int lbl = label[b * L_ + l];
        unsigned m = __ballot_sync(0xffffffffu, lbl == c);
        if (lbl == c) {
            int pos = cnt + __popc(m & ((1u << lane) - 1u));
            g_idx[b][c][pos] = l;
        }
        cnt += __popc(m);
    }
    if (lane == 0) g_cnt[b][c] = cnt;
}

// ===========================================================================
// mma.sync / ldmatrix helpers (family-common PTX, valid on target sm_103)
// ===========================================================================
__device__ __forceinline__ uint32_t smem_u32(const void* p) {
    uint32_t a;
    asm("{ .reg .u64 t; cvta.to.shared.u64 t, %1; cvt.u32.u64 %0, t; }"
        : "=r"(a) : "l"(p));
    return a;
}
__device__ __forceinline__ void ldsm4(uint32_t addr, uint32_t* r) {
    asm volatile("ldmatrix.sync.aligned.m8n8.x4.shared.b16 {%0,%1,%2,%3}, [%4];"
                 : "=r"(r[0]), "=r"(r[1]), "=r"(r[2]), "=r"(r[3]) : "r"(addr));
}
__device__ __forceinline__ void ldsm4t(uint32_t addr, uint32_t* r) {
    asm volatile("ldmatrix.sync.aligned.m8n8.x4.trans.shared.b16 {%0,%1,%2,%3}, [%4];"
                 : "=r"(r[0]), "=r"(r[1]), "=r"(r[2]), "=r"(r[3]) : "r"(addr));
}
__device__ __forceinline__ void mma16816(float* c, const uint32_t* a,
                                         uint32_t b0, uint32_t b1) {
    asm volatile(
        "mma.sync.aligned.m16n8k16.row.col.f32.f16.f16.f32 "
        "{%0,%1,%2,%3}, {%4,%5,%6,%7}, {%8,%9}, {%0,%1,%2,%3};"
        : "+f"(c[0]), "+f"(c[1]), "+f"(c[2]), "+f"(c[3])
        : "r"(a[0]), "r"(a[1]), "r"(a[2]), "r"(a[3]), "r"(b0), "r"(b1));
}
// fp16 split: x = hi + lo; hi*hi exact in fp32, dropped lo*lo ~2^-22 rel
__device__ __forceinline__ void split2(float x0, float x1,
                                       uint32_t& hi, uint32_t& lo) {
    __half h0 = __float2half_rn(x0), h1 = __float2half_rn(x1);
    __half l0 = __float2half_rn(x0 - __half2float(h0));
    __half l1 = __float2half_rn(x1 - __half2float(h1));
    __half2 hp = __halves2half2(h0, h1), lp = __halves2half2(l0, l1);
    hi = *reinterpret_cast<uint32_t*>(&hp);
    lo = *reinterpret_cast<uint32_t*>(&lp);
}
// byte offset in a 96x128 f16 tile, 256B rows, 16B-chunk XOR swizzle
__device__ __forceinline__ uint32_t swz(int row, int col) {
    return (uint32_t)(row * 256) + (uint32_t)((((col >> 3) ^ (row & 7)) & 15) << 4)
         + (uint32_t)((col & 7) << 1);
}
__device__ __forceinline__ uint32_t swz16(int row, int ch) {   // 16B chunk index
    return (uint32_t)(row * 256) + (uint32_t)(((ch ^ (row & 7)) & 15) << 4);
}

// smem layout (bytes): 96-row tiles; Q tiles become P tiles; K tiles become V
#define SM_PHI  0
#define SM_PLO  24576
#define SM_KVHI 49152
#define SM_KVLO 73728
#define SM_IDX  98304    /* 96 ints, padded */
#define SM_RED  98816    /* redm[2][96], redl[2][96] */
#define SMEM_TOTAL 100352

// Dead-code-in-practice fallback for nc > 96 (slow, simple, correct).
__device__ __noinline__ void attn_fallback(int b, int c, int k, int nc,
                                           const int* idxs,
                                           const float* query,
                                           const float* value,
                                           float* out) {
    const float scale = 0.08838834764831845f;
    for (int r = threadIdx.x; r < nc; r += blockDim.x) {
        int i = idxs[r];
        const float* q = query + (((size_t)b * L_ + i) * V_ + k) * D_;
        float m = -1e30f;
        for (int jj = 0; jj < nc; jj++) {
            const float* kr = g_sumK + ((size_t)b * L_ + idxs[jj]) * D_;
            float s = 0.f;
            for (int d = 0; d < D_; d++) s += q[d] * kr[d];
            m = fmaxf(m, s * scale);
        }
        float l = 0.f;
        for (int jj = 0; jj < nc; jj++) {
            const float* kr = g_sumK + ((size_t)b * L_ + idxs[jj]) * D_;
            float s = 0.f;
            for (int d = 0; d < D_; d++) s += q[d] * kr[d];
            l += __expf(s * scale - m);
        }
        for (int d0 = 0; d0 < D_; d0 += 32) {
            float acc[32];
            for (int e = 0; e < 32; e++) acc[e] = 0.f;
            for (int jj = 0; jj < nc; jj++) {
                const float* kr = g_sumK + ((size_t)b * L_ + idxs[jj]) * D_;
                float s = 0.f;
                for (int d = 0; d < D_; d++) s += q[d] * kr[d];
                float p = __expf(s * scale - m) / l;
                const float* vr = value +
                    (((size_t)b * L_ + idxs[jj]) * V_ + k) * D_ + d0;
                for (int e = 0; e < 32; e++) acc[e] += p * vr[e];
            }
            float* dst = out + (((size_t)b * L_ + i) * V_ + k) * D_ + d0;
            for (int e = 0; e < 32; e++) dst[e] = acc[e];
        }
    }
}

// ===========================================================================
// Kernel 3: HMMA clustered attention, 2 CTAs/SM, term-major mma ordering.
// ===========================================================================
extern __shared__ char smx[];

__global__ __launch_bounds__(256, 2)
void attn_mma_kernel(const float* __restrict__ query,
                     const float* __restrict__ value,
                     float* __restrict__ out) {
    const int k = blockIdx.x, c = blockIdx.y, b = blockIdx.z;
    const int tid = threadIdx.x;
    const int lane = tid & 31;
    const int w = tid >> 5;
    const int half = w & 1;
    const int pairid = w >> 1;
    const float scale = 0.08838834764831845f;

    const int nc = g_cnt[b][c];
    if (nc == 0) return;
    int* idxs = (int*)(smx + SM_IDX);
    for (int t = tid; t < nc && t < 128; t += 256)
        idxs[t] = g_idx[b][c][t];            // only first <=96 used by fast path
    __syncthreads();
    if (nc > NR_MAX) {
        // reload full list into registers path (fallback reads g_idx directly)
        attn_fallback(b, c, k, nc, g_idx[b][c], query, value, out);
        return;
    }

    const int nr = (nc + 15) & ~15;           // <= 96
    const int npair = nr >> 4;                // <= 6
    const int niter = (npair + 3) >> 2;       // <= 2

    // ---- gather Q (fp32->split) and K (pre-split fp16) -------------------
    for (int t = tid; t < nr * 64; t += 256) {        // Q: 64 float2 per row
        int row = t >> 6, cp = t & 63;
        float2 x = make_float2(0.f, 0.f);
        if (row < nc)
            x = ((const float2*)query)[
                    ((((size_t)b * L_ + idxs[row]) * V_ + k) << 6) + cp];
        uint32_t hi, lo;
        split2(x.x * scale, x.y * scale, hi, lo);
        uint32_t off = swz(row, cp << 1);
        *(uint32_t*)(smx + SM_PHI + off) = hi;
        *(uint32_t*)(smx + SM_PLO + off) = lo;
    }
    for (int t = tid; t < nr * 16; t += 256) {        // K: 16 uint4 per row
        int row = t >> 4, ch = t & 15;
        uint4 hv = make_uint4(0, 0, 0, 0), lv = hv;
        if (row < nc) {
            size_t base = (((size_t)b * L_ + idxs[row]) << 4) + ch;
            hv = ((const uint4*)g_sKh)[base];
            lv = ((const uint4*)g_sKl)[base];
        }
        uint32_t off = swz16(row, ch);
        *(uint4*)(smx + SM_KVHI + off) = hv;
        *(uint4*)(smx + SM_KVLO + off) = lv;
    }
    __syncthreads();

    const uint32_t sb  = smem_u32(smx);
    const uint32_t phi = sb + SM_PHI, plo = sb + SM_PLO;
    const uint32_t kvh = sb + SM_KVHI, kvl = sb + SM_KVLO;
    float* redm = (float*)(smx + SM_RED);     // [2][96]
    float* redl = redm + 192;

    const int g  = lane >> 3;
    const int rA = (lane & 7) + ((g & 1) << 3);
    const int cA = ((g >> 1) & 1) << 3;
    const int rB = (lane & 7) + (((g >> 1) & 1) << 3);
    const int cB = (g & 1) << 3;
    const int colb = (lane & 3) << 1;
    const int qr = lane >> 2;

    // =========== phase 1: all S strips + softmax + P writes ================
    for (int it = 0; it < niter; it++) {
        const int strip = it * 4 + pairid;
        const int row0 = strip * 16;
        const bool active = row0 < nr;
        const int r1 = row0 + qr, r2 = r1 + 8;

        float cS[8][4];
#pragma unroll
        for (int n = 0; n < 8; n++)
#pragma unroll
            for (int r = 0; r < 4; r++) cS[n][r] = 0.f;

        if (active) {
#pragma unroll
            for (int s = 0; s < 8; s++) {
                uint32_t ah[4], al[4], bh[4][4], bl[4][4];
                ldsm4(phi + swz(row0 + rA, s * 16 + cA), ah);
                ldsm4(plo + swz(row0 + rA, s * 16 + cA), al);
#pragma unroll
                for (int u = 0; u < 4; u++) {
                    int ti = half + 2 * u;
                    if (ti < npair) {
                        ldsm4(kvh + swz(16 * ti + rB, s * 16 + cB), bh[u]);
                        ldsm4(kvl + swz(16 * ti + rB, s * 16 + cB), bl[u]);
                    }
                }
                // term-major: same-accumulator distance = 8 mmas
#pragma unroll
                for (int u = 0; u < 4; u++) {
                    if (half + 2 * u < npair) {
                        mma16816(cS[2 * u],     ah, bh[u][0], bh[u][1]);
                        mma16816(cS[2 * u + 1], ah, bh[u][2], bh[u][3]);
                    }
                }
#pragma unroll
                for (int u = 0; u < 4; u++) {
                    if (half + 2 * u < npair) {
                        mma16816(cS[2 * u],     ah, bl[u][0], bl[u][1]);
                        mma16816(cS[2 * u + 1], ah, bl[u][2], bl[u][3]);
                    }
                }
#pragma unroll
                for (int u = 0; u < 4; u++) {
                    if (half + 2 * u < npair) {
                        mma16816(cS[2 * u],     al, bh[u][0], bh[u][1]);
                        mma16816(cS[2 * u + 1], al, bh[u][2], bh[u][3]);
                    }
                }
            }

            // partial row max
            float m0 = -1e30f, m1 = -1e30f;
#pragma unroll
            for (int u = 0; u < 4; u++) {
                int ti = half + 2 * u;
                if (ti < npair) {
#pragma unroll
                    for (int sub = 0; sub < 2; sub++) {
                        int n = 2 * u + sub;
                        int c0 = ti * 16 + sub * 8 + colb;
                        if (c0 < nc)     { m0 = fmaxf(m0, cS[n][0]); m1 = fmaxf(m1, cS[n][2]); }
                        if (c0 + 1 < nc) { m0 = fmaxf(m0, cS[n][1]); m1 = fmaxf(m1, cS[n][3]); }
                    }
                }
            }
            m0 = fmaxf(m0, __shfl_xor_sync(0xffffffffu, m0, 1));
            m0 = fmaxf(m0, __shfl_xor_sync(0xffffffffu, m0, 2));
            m1 = fmaxf(m1, __shfl_xor_sync(0xffffffffu, m1, 1));
            m1 = fmaxf(m1, __shfl_xor_sync(0xffffffffu, m1, 2));
            if ((lane & 3) == 0) {
                redm[half * 96 + r1] = m0;
                redm[half * 96 + r2] = m1;
            }
        }
        __syncthreads();   // partial maxes visible

        if (active) {
            float mt0 = fmaxf(redm[r1], redm[96 + r1]);
            float mt1 = fmaxf(redm[r2], redm[96 + r2]);
            float l0 = 0.f, l1 = 0.f;
#pragma unroll
            for (int u = 0; u < 4; u++) {
                int ti = half + 2 * u;
                if (ti < npair) {
#pragma unroll
                    for (int sub = 0; sub < 2; sub++) {
                        int n = 2 * u + sub;
                        int c0 = ti * 16 + sub * 8 + colb;
                        float p0 = (c0     < nc) ? __expf(cS[n][0] - mt0) : 0.f;
                        float p1 = (c0 + 1 < nc) ? __expf(cS[n][1] - mt0) : 0.f;
                        float p2 = (c0     < nc) ? __expf(cS[n][2] - mt1) : 0.f;
                        float p3 = (c0 + 1 < nc) ? __expf(cS[n][3] - mt1) : 0.f;
                        l0 += p0 + p1; l1 += p2 + p3;
                        uint32_t hi, lo;
                        split2(p0, p1, hi, lo);
                        *(uint32_t*)(smx + SM_PHI + swz(r1, c0)) = hi;
                        *(uint32_t*)(smx + SM_PLO + swz(r1, c0)) = lo;
                        split2(p2, p3, hi, lo);
                        *(uint32_t*)(smx + SM_PHI + swz(r2, c0)) = hi;
                        *(uint32_t*)(smx + SM_PLO + swz(r2, c0)) = lo;
                    }
                }
            }
            l0 += __shfl_xor_sync(0xffffffffu, l0, 1);
            l0 += __shfl_xor_sync(0xffffffffu, l0, 2);
            l1 += __shfl_xor_sync(0xffffffffu, l1, 1);
            l1 += __shfl_xor_sync(0xffffffffu, l1, 2);
            if ((lane & 3) == 0) {
                redl[half * 96 + r1] = l0;
                redl[half * 96 + r2] = l1;
            }
        }
    }
    __syncthreads();   // all K reads + all P/l writes complete

    // =========== phase 2: convert V over the K tiles =======================
    for (int t = tid; t < nr * 64; t += 256) {
        int row = t >> 6, cp = t & 63;
        float2 x = make_float2(0.f, 0.f);
        if (row < nc)
            x = ((const float2*)value)[
                    ((((size_t)b * L_ + idxs[row]) * V_ + k) << 6) + cp];
        uint32_t hi, lo;
        split2(x.x, x.y, hi, lo);
        uint32_t off = swz(row, cp << 1);
        *(uint32_t*)(smx + SM_KVHI + off) = hi;
        *(uint32_t*)(smx + SM_KVLO + off) = lo;
    }
    __syncthreads();

    // =========== phase 3: all PV strips + epilogue =========================
    for (int it = 0; it < niter; it++) {
        const int strip = it * 4 + pairid;
        const int row0 = strip * 16;
        if (row0 >= nr) continue;
        const int r1 = row0 + qr, r2 = r1 + 8;

        float o[8][4];
#pragma unroll
        for (int n = 0; n < 8; n++)
#pragma unroll
            for (int r = 0; r < 4; r++) o[n][r] = 0.f;

#pragma unroll
        for (int kt = 0; kt < 6; kt++) {
            if (kt < npair) {
                uint32_t ph[4], pl[4], vh[4][4], vl[4][4];
                ldsm4(phi + swz(row0 + rA, kt * 16 + cA), ph);
                ldsm4(plo + swz(row0 + rA, kt * 16 + cA), pl);
#pragma unroll
                for (int dq = 0; dq < 4; dq++) {
                    int dp = half * 4 + dq;
                    ldsm4t(kvh + swz(16 * kt + rA, 16 * dp + cA), vh[dq]);
                    ldsm4t(kvl + swz(16 * kt + rA, 16 * dp + cA), vl[dq]);
                }
#pragma unroll
                for (int dq = 0; dq < 4; dq++) {
                    mma16816(o[2 * dq],     ph, vh[dq][0], vh[dq][1]);
                    mma16816(o[2 * dq + 1], ph, vh[dq][2], vh[dq][3]);
                }
#pragma unroll
                for (int dq = 0; dq < 4; dq++) {
                    mma16816(o[2 * dq],     ph, vl[dq][0], vl[dq][1]);
                    mma16816(o[2 * dq + 1], ph, vl[dq][2], vl[dq][3]);
                }
#pragma unroll
                for (int dq = 0; dq < 4; dq++) {
                    mma16816(o[2 * dq],     pl, vh[dq][0], vh[dq][1]);
                    mma16816(o[2 * dq + 1], pl, vh[dq][2], vh[dq][3]);
                }
            }
        }

        float lt0 = redl[r1] + redl[96 + r1];
        float lt1 = redl[r2] + redl[96 + r2];
        float i0 = 1.f / lt0, i1 = 1.f / lt1;
        float* d1 = (r1 < nc)
            ? out + (((size_t)b * L_ + idxs[r1]) * V_ + k) * D_ : nullptr;
        float* d2 = (r2 < nc)
            ? out + (((size_t)b * L_ + idxs[r2]) * V_ + k) * D_ : nullptr;
#pragma unroll
        for (int n = 0; n < 8; n++) {
            int col = half * 64 + n * 8 + colb;
            if (d1) *(float2*)(d1 + col) = make_float2(o[n][0] * i0, o[n][1] * i0);
            if (d2) *(float2*)(d2 + col) = make_float2(o[n][2] * i1, o[n][3] * i1);
        }
    }
}

extern "C" void kernel_launch(void* const* d_in, const int* in_sizes, int n_in,
                              void* d_out, int out_size) {
    (void)in_sizes; (void)n_in; (void)out_size;
    const float* query = (const float*)d_in[0];
    const float* key   = (const float*)d_in[1];
    const float* value = (const float*)d_in[2];
    const int*   label = (const int*)d_in[3];
    float* out = (float*)d_out;

    prof_pad_kernel<<<1, 32>>>();
    sumk_kernel<<<B_ * L_, 256>>>((const float4*)key);
    build_idx_kernel<<<dim3(NC_, B_), 32>>>(label);
    cudaFuncSetAttribute(attn_mma_kernel,
                         cudaFuncAttributeMaxDynamicSharedMemorySize, SMEM_TOTAL);
    attn_mma_kernel<<<dim3(V_, NC_, B_), 256, SMEM_TOTAL>>>(query, value, out);
}

// round 8
// speedup vs baseline: 2.6481x; 2.0544x over previous
#include <cuda_runtime.h>
#include <cuda_fp16.h>
#include <cstdint>

#define B_ 2
#define L_ 512
#define V_ 64
#define D_ 128
#define NC_ 8
#define NR_MAX 96

// ---- static device scratch (no allocations allowed) ----
__device__ float  g_sumK[B_ * L_ * D_];
__device__ __half g_sKh[B_ * L_ * D_];
__device__ __half g_sKl[B_ * L_ * D_];
__device__ __half g_Qh[B_ * L_ * V_ * D_];
__device__ __half g_Ql[B_ * L_ * V_ * D_];
__device__ __half g_Vh[B_ * L_ * V_ * D_];
__device__ __half g_Vl[B_ * L_ * V_ * D_];
__device__ int    g_idx[B_][NC_][L_];
__device__ int    g_cnt[B_][NC_];

#define SCALE_ 0.08838834764831845f

// ===========================================================================
// Kernel A: stream-split Q (scale folded) and V into fp16 hi/lo
// ===========================================================================
__device__ __forceinline__ uint32_t packh2(float a, float b2) {
    __half2 h = __halves2half2(__float2half_rn(a), __float2half_rn(b2));
    return *reinterpret_cast<uint32_t*>(&h);
}
__global__ void split_kernel(const float4* __restrict__ q,
                             const float4* __restrict__ v) {
    const int N4 = B_ * L_ * V_ * D_ / 4;              // 2097152
    bool isV = blockIdx.x >= 2048;
    const float4* src = isV ? v : q;
    uint2* dh = (uint2*)(isV ? g_Vh : g_Qh);
    uint2* dl = (uint2*)(isV ? g_Vl : g_Ql);
    const float sc = isV ? 1.f : SCALE_;
    int base = (blockIdx.x & 2047) * 256 + threadIdx.x;
#pragma unroll
    for (int u = 0; u < 4; u++) {
        int i = base + u * (N4 / 4);
        float4 x = src[i];
        x.x *= sc; x.y *= sc; x.z *= sc; x.w *= sc;
        __half hx = __float2half_rn(x.x), hy = __float2half_rn(x.y);
        __half hz = __float2half_rn(x.z), hw = __float2half_rn(x.w);
        uint2 hv, lv;
        { __half2 t = __halves2half2(hx, hy); hv.x = *(uint32_t*)&t; }
        { __half2 t = __halves2half2(hz, hw); hv.y = *(uint32_t*)&t; }
        lv.x = packh2(x.x - __half2float(hx), x.y - __half2float(hy));
        lv.y = packh2(x.z - __half2float(hz), x.w - __half2float(hw));
        dh[i] = hv; dl[i] = lv;
    }
}

// ===========================================================================
// Kernel B: sumK = sum_v key (fp32 + fp16 hi/lo split)
// ===========================================================================
__global__ void sumk_kernel(const float4* __restrict__ key4) {
    __shared__ float4 part[256];
    int bl = blockIdx.x;
    int g = threadIdx.x & 31, q = threadIdx.x >> 5;
    const float4* p = key4 + (size_t)bl * (V_ * D_ / 4) + (size_t)(q * 8) * (D_ / 4) + g;
    float4 s = make_float4(0.f, 0.f, 0.f, 0.f);
#pragma unroll
    for (int v = 0; v < 8; v++) {
        float4 t = p[(size_t)v * (D_ / 4)];
        s.x += t.x; s.y += t.y; s.z += t.z; s.w += t.w;
    }
    part[threadIdx.x] = s;
    __syncthreads();
    if (q < 4) {
        float4 a = part[threadIdx.x], b2 = part[threadIdx.x + 128];
        part[threadIdx.x] = make_float4(a.x + b2.x, a.y + b2.y, a.z + b2.z, a.w + b2.w);
    }
    __syncthreads();
    if (q == 0) {
        float4 a = part[g], b2 = part[32 + g], c2 = part[64 + g], d2 = part[96 + g];
        float4 r = make_float4(a.x + b2.x + c2.x + d2.x, a.y + b2.y + c2.y + d2.y,
                               a.z + b2.z + c2.z + d2.z, a.w + b2.w + c2.w + d2.w);
        ((float4*)g_sumK)[(size_t)bl * 32 + g] = r;
        __half hx = __float2half_rn(r.x), hy = __float2half_rn(r.y);
        __half hz = __float2half_rn(r.z), hw = __float2half_rn(r.w);
        size_t o = (size_t)bl * 64 + g * 2;
        { __half2 t = __halves2half2(hx, hy); ((uint32_t*)g_sKh)[o] = *(uint32_t*)&t; }
        { __half2 t = __halves2half2(hz, hw); ((uint32_t*)g_sKh)[o + 1] = *(uint32_t*)&t; }
        ((uint32_t*)g_sKl)[o] =
            packh2(r.x - __half2float(hx), r.y - __half2float(hy));
        ((uint32_t*)g_sKl)[o + 1] =
            packh2(r.z - __half2float(hz), r.w - __half2float(hw));
    }
}

// ===========================================================================
// Kernel C: deterministic per-(b,c) index lists via ballot compaction
// ===========================================================================
__global__ void build_idx_kernel(const int* __restrict__ label) {
    int c = blockIdx.x, b = blockIdx.y;
    int lane = threadIdx.x;
    int cnt = 0;
    for (int l0 = 0; l0 < L_; l0 += 32) {
        int l = l0 + lane;
        int lbl = label[b * L_ + l];
        unsigned m = __ballot_sync(0xffffffffu, lbl == c);
        if (lbl == c) {
            int pos = cnt + __popc(m & ((1u << lane) - 1u));
            g_idx[b][c][pos] = l;
        }
        cnt += __popc(m);
    }
    if (lane == 0) g_cnt[b][c] = cnt;
}

// ===========================================================================
// PTX helpers (family-common, valid on target sm_103)
// ===========================================================================
__device__ __forceinline__ uint32_t smem_u32(const void* p) {
    uint32_t a;
    asm("{ .reg .u64 t; cvta.to.shared.u64 t, %1; cvt.u32.u64 %0, t; }"
        : "=r"(a) : "l"(p));
    return a;
}
__device__ __forceinline__ void cpa16(uint32_t dst, const void* src) {
    asm volatile("cp.async.cg.shared.global [%0], [%1], 16;"
                 :: "r"(dst), "l"(src));
}
__device__ __forceinline__ void cpa_commit_wait() {
    asm volatile("cp.async.commit_group;");
    asm volatile("cp.async.wait_group 0;" ::: "memory");
}
__device__ __forceinline__ void ldsm4(uint32_t addr, uint32_t* r) {
    asm volatile("ldmatrix.sync.aligned.m8n8.x4.shared.b16 {%0,%1,%2,%3}, [%4];"
                 : "=r"(r[0]), "=r"(r[1]), "=r"(r[2]), "=r"(r[3]) : "r"(addr));
}
__device__ __forceinline__ void ldsm4t(uint32_t addr, uint32_t* r) {
    asm volatile("ldmatrix.sync.aligned.m8n8.x4.trans.shared.b16 {%0,%1,%2,%3}, [%4];"
                 : "=r"(r[0]), "=r"(r[1]), "=r"(r[2]), "=r"(r[3]) : "r"(addr));
}
__device__ __forceinline__ void mma16816(float* c, const uint32_t* a,
                                         uint32_t b0, uint32_t b1) {
    asm volatile(
        "mma.sync.aligned.m16n8k16.row.col.f32.f16.f16.f32 "
        "{%0,%1,%2,%3}, {%4,%5,%6,%7}, {%8,%9}, {%0,%1,%2,%3};"
        : "+f"(c[0]), "+f"(c[1]), "+f"(c[2]), "+f"(c[3])
        : "r"(a[0]), "r"(a[1]), "r"(a[2]), "r"(a[3]), "r"(b0), "r"(b1));
}
__device__ __forceinline__ void split2(float x0, float x1,
                                       uint32_t& hi, uint32_t& lo) {
    __half h0 = __float2half_rn(x0), h1 = __float2half_rn(x1);
    __half l0 = __float2half_rn(x0 - __half2float(h0));
    __half l1 = __float2half_rn(x1 - __half2float(h1));
    __half2 hp = __halves2half2(h0, h1), lp = __halves2half2(l0, l1);
    hi = *reinterpret_cast<uint32_t*>(&hp);
    lo = *reinterpret_cast<uint32_t*>(&lp);
}
// byte offset in a 96x128 f16 tile, 256B rows, 16B-chunk XOR swizzle
__device__ __forceinline__ uint32_t swz(int row, int col) {
    return (uint32_t)(row * 256) + (uint32_t)((((col >> 3) ^ (row & 7)) & 15) << 4)
         + (uint32_t)((col & 7) << 1);
}
__device__ __forceinline__ uint32_t swz16(int row, int ch) {
    return (uint32_t)(row * 256) + (uint32_t)(((ch ^ (row & 7)) & 15) << 4);
}

// smem layout: Q tiles become P tiles; K tiles become V tiles
#define SM_PHI  0
#define SM_PLO  24576
#define SM_KVHI 49152
#define SM_KVLO 73728
#define SM_IDX  98304    /* 96 ints */
#define SM_ORD  98688    /* 1 int   */
#define SM_RED  98816    /* redm[2][96], redl[2][96] */
#define SMEM_TOTAL 100352

// Dead-code-in-practice fallback for nc > 96 (slow, simple, correct).
__device__ __noinline__ void attn_fallback(int b, int c, int k, int nc,
                                           const int* idxs,
                                           const float* query,
                                           const float* value,
                                           float* out) {
    for (int r = threadIdx.x; r < nc; r += blockDim.x) {
        int i = idxs[r];
        const float* q = query + (((size_t)b * L_ + i) * V_ + k) * D_;
        float m = -1e30f;
        for (int jj = 0; jj < nc; jj++) {
            const float* kr = g_sumK + ((size_t)b * L_ + idxs[jj]) * D_;
            float s = 0.f;
            for (int d = 0; d < D_; d++) s += q[d] * kr[d];
            m = fmaxf(m, s * SCALE_);
        }
        float l = 0.f;
        for (int jj = 0; jj < nc; jj++) {
            const float* kr = g_sumK + ((size_t)b * L_ + idxs[jj]) * D_;
            float s = 0.f;
            for (int d = 0; d < D_; d++) s += q[d] * kr[d];
            l += __expf(s * SCALE_ - m);
        }
        for (int d0 = 0; d0 < D_; d0 += 32) {
            float acc[32];
            for (int e = 0; e < 32; e++) acc[e] = 0.f;
            for (int jj = 0; jj < nc; jj++) {
                const float* kr = g_sumK + ((size_t)b * L_ + idxs[jj]) * D_;
                float s = 0.f;
                for (int d = 0; d < D_; d++) s += q[d] * kr[d];
                float p = __expf(s * SCALE_ - m) / l;
                const float* vr = value +
                    (((size_t)b * L_ + idxs[jj]) * V_ + k) * D_ + d0;
                for (int e = 0; e < 32; e++) acc[e] += p * vr[e];
            }
            float* dst = out + (((size_t)b * L_ + i) * V_ + k) * D_ + d0;
            for (int e = 0; e < 32; e++) dst[e] = acc[e];
        }
    }
}

// ===========================================================================
// Kernel D: HMMA clustered attention. cp.async fills, LPT cluster order.
// ===========================================================================
extern __shared__ char smx[];

__global__ __launch_bounds__(256, 2)
void attn_mma_kernel(const float* __restrict__ query,
                     const float* __restrict__ value,
                     float* __restrict__ out) {
    const int k = blockIdx.x, cl = blockIdx.y;
    const int tid = threadIdx.x;
    const int lane = tid & 31;
    const int w = tid >> 5;
    const int half = w & 1;
    const int pairid = w >> 1;

    // ---- LPT: rank clusters by descending count (deterministic tie-break)
    if (w == 0) {
        int key = -1;
        if (lane < 16) key = (g_cnt[lane >> 3][lane & 7] << 4) | (15 - lane);
        int rank = 0;
#pragma unroll
        for (int j = 0; j < 16; j++) {
            int other = __shfl_sync(0xffffffffu, key, j);
            if (lane < 16 && other > key) rank++;
        }
        if (lane < 16 && rank == cl) *(int*)(smx + SM_ORD) = lane;
    }
    __syncthreads();
    const int ordv = *(int*)(smx + SM_ORD);
    const int b = ordv >> 3, c = ordv & 7;

    const int nc = g_cnt[b][c];
    if (nc == 0) return;
    int* idxs = (int*)(smx + SM_IDX);
    for (int t = tid; t < nc && t < NR_MAX; t += 256) idxs[t] = g_idx[b][c][t];
    __syncthreads();
    if (nc > NR_MAX) {
        attn_fallback(b, c, k, nc, g_idx[b][c], query, value, out);
        return;
    }

    const int nr = (nc + 15) & ~15;           // <= 96
    const int npair = nr >> 4;                // <= 6
    const int niter = (npair + 3) >> 2;       // <= 2

    const uint32_t sb  = smem_u32(smx);
    const uint32_t phi = sb + SM_PHI, plo = sb + SM_PLO;
    const uint32_t kvh = sb + SM_KVHI, kvl = sb + SM_KVLO;

    // ---- async fill: Q (pre-split, scale folded) + K (pre-split sumK) ----
    for (int t = tid; t < nr * 16; t += 256) {
        int row = t >> 4, ch = t & 15;
        uint32_t so = swz16(row, ch);
        if (row < nc) {
            size_t qb = ((((size_t)b * L_ + idxs[row]) * V_ + k) << 8) + (ch << 4);
            size_t kb = (((size_t)b * L_ + idxs[row]) << 8) + (ch << 4);
            cpa16(phi + so, (const char*)g_Qh + qb);
            cpa16(plo + so, (const char*)g_Ql + qb);
            cpa16(kvh + so, (const char*)g_sKh + kb);
            cpa16(kvl + so, (const char*)g_sKl + kb);
        } else {
            uint4 z = make_uint4(0, 0, 0, 0);
            *(uint4*)(smx + SM_PHI + so) = z;
            *(uint4*)(smx + SM_PLO + so) = z;
            *(uint4*)(smx + SM_KVHI + so) = z;
            *(uint4*)(smx + SM_KVLO + so) = z;
        }
    }
    cpa_commit_wait();
    __syncthreads();

    float* redm = (float*)(smx + SM_RED);     // [2][96]
    float* redl = redm + 192;

    const int g  = lane >> 3;
    const int rA = (lane & 7) + ((g & 1) << 3);
    const int cA = ((g >> 1) & 1) << 3;
    const int rB = (lane & 7) + (((g >> 1) & 1) << 3);
    const int cB = (g & 1) << 3;
    const int colb = (lane & 3) << 1;
    const int qr = lane >> 2;

    // =========== phase 1: all S strips + softmax + P writes ================
    for (int it = 0; it < niter; it++) {
        const int strip = it * 4 + pairid;
        const int row0 = strip * 16;
        const bool active = row0 < nr;
        const int r1 = row0 + qr, r2 = r1 + 8;

        float cS[8][4];
#pragma unroll
        for (int n = 0; n < 8; n++)
#pragma unroll
            for (int r = 0; r < 4; r++) cS[n][r] = 0.f;

        if (active) {
#pragma unroll
            for (int s = 0; s < 8; s++) {
                uint32_t ah[4], al[4], bh[4][4], bl[4][4];
                ldsm4(phi + swz(row0 + rA, s * 16 + cA), ah);
                ldsm4(plo + swz(row0 + rA, s * 16 + cA), al);
#pragma unroll
                for (int u = 0; u < 4; u++) {
                    int ti = half + 2 * u;
                    if (ti < npair) {
                        ldsm4(kvh + swz(16 * ti + rB, s * 16 + cB), bh[u]);
                        ldsm4(kvl + swz(16 * ti + rB, s * 16 + cB), bl[u]);
                    }
                }
#pragma unroll
                for (int u = 0; u < 4; u++) {
                    if (half + 2 * u < npair) {
                        mma16816(cS[2 * u],     ah, bh[u][0], bh[u][1]);
                        mma16816(cS[2 * u + 1], ah, bh[u][2], bh[u][3]);
                    }
                }
#pragma unroll
                for (int u = 0; u < 4; u++) {
                    if (half + 2 * u < npair) {
                        mma16816(cS[2 * u],     ah, bl[u][0], bl[u][1]);
                        mma16816(cS[2 * u + 1], ah, bl[u][2], bl[u][3]);
                    }
                }
#pragma unroll
                for (int u = 0; u < 4; u++) {
                    if (half + 2 * u < npair) {
                        mma16816(cS[2 * u],     al, bh[u][0], bh[u][1]);
                        mma16816(cS[2 * u + 1], al, bh[u][2], bh[u][3]);
                    }
                }
            }

            float m0 = -1e30f, m1 = -1e30f;
#pragma unroll
            for (int u = 0; u < 4; u++) {
                int ti = half + 2 * u;
                if (ti < npair) {
#pragma unroll
                    for (int sub = 0; sub < 2; sub++) {
                        int n = 2 * u + sub;
                        int c0 = ti * 16 + sub * 8 + colb;
                        if (c0 < nc)     { m0 = fmaxf(m0, cS[n][0]); m1 = fmaxf(m1, cS[n][2]); }
                        if (c0 + 1 < nc) { m0 = fmaxf(m0, cS[n][1]); m1 = fmaxf(m1, cS[n][3]); }
                    }
                }
            }
            m0 = fmaxf(m0, __shfl_xor_sync(0xffffffffu, m0, 1));
            m0 = fmaxf(m0, __shfl_xor_sync(0xffffffffu, m0, 2));
            m1 = fmaxf(m1, __shfl_xor_sync(0xffffffffu, m1, 1));
            m1 = fmaxf(m1, __shfl_xor_sync(0xffffffffu, m1, 2));
            if ((lane & 3) == 0) {
                redm[half * 96 + r1] = m0;
                redm[half * 96 + r2] = m1;
            }
        }
        __syncthreads();

        if (active) {
            float mt0 = fmaxf(redm[r1], redm[96 + r1]);
            float mt1 = fmaxf(redm[r2], redm[96 + r2]);
            float l0 = 0.f, l1 = 0.f;
#pragma unroll
            for (int u = 0; u < 4; u++) {
                int ti = half + 2 * u;
                if (ti < npair) {
#pragma unroll
                    for (int sub = 0; sub < 2; sub++) {
                        int n = 2 * u + sub;
                        int c0 = ti * 16 + sub * 8 + colb;
                        float p0 = (c0     < nc) ? __expf(cS[n][0] - mt0) : 0.f;
                        float p1 = (c0 + 1 < nc) ? __expf(cS[n][1] - mt0) : 0.f;
                        float p2 = (c0     < nc) ? __expf(cS[n][2] - mt1) : 0.f;
                        float p3 = (c0 + 1 < nc) ? __expf(cS[n][3] - mt1) : 0.f;
                        l0 += p0 + p1; l1 += p2 + p3;
                        uint32_t hi, lo;
                        split2(p0, p1, hi, lo);
                        *(uint32_t*)(smx + SM_PHI + swz(r1, c0)) = hi;
                        *(uint32_t*)(smx + SM_PLO + swz(r1, c0)) = lo;
                        split2(p2, p3, hi, lo);
                        *(uint32_t*)(smx + SM_PHI + swz(r2, c0)) = hi;
                        *(uint32_t*)(smx + SM_PLO + swz(r2, c0)) = lo;
                    }
                }
            }
            l0 += __shfl_xor_sync(0xffffffffu, l0, 1);
            l0 += __shfl_xor_sync(0xffffffffu, l0, 2);
            l1 += __shfl_xor_sync(0xffffffffu, l1, 1);
            l1 += __shfl_xor_sync(0xffffffffu, l1, 2);
            if ((lane & 3) == 0) {
                redl[half * 96 + r1] = l0;
                redl[half * 96 + r2] = l1;
            }
        }
    }
    __syncthreads();   // all K reads + all P/l writes complete

    // =========== phase 2: async V copy over the K tiles ====================
    for (int t = tid; t < nr * 16; t += 256) {
        int row = t >> 4, ch = t & 15;
        uint32_t so = swz16(row, ch);
        if (row < nc) {
            size_t vb = ((((size_t)b * L_ + idxs[row]) * V_ + k) << 8) + (ch << 4);
            cpa16(kvh + so, (const char*)g_Vh + vb);
            cpa16(kvl + so, (const char*)g_Vl + vb);
        } else {
            uint4 z = make_uint4(0, 0, 0, 0);
            *(uint4*)(smx + SM_KVHI + so) = z;
            *(uint4*)(smx + SM_KVLO + so) = z;
        }
    }
    cpa_commit_wait();
    __syncthreads();

    // =========== phase 3: all PV strips + epilogue =========================
    for (int it = 0; it < niter; it++) {
        const int strip = it * 4 + pairid;
        const int row0 = strip * 16;
        if (row0 >= nr) continue;
        const int r1 = row0 + qr, r2 = r1 + 8;

        float o[8][4];
#pragma unroll
        for (int n = 0; n < 8; n++)
#pragma unroll
            for (int r = 0; r < 4; r++) o[n][r] = 0.f;

#pragma unroll
        for (int kt = 0; kt < 6; kt++) {
            if (kt < npair) {
                uint32_t ph[4], pl[4], vh[4][4], vl[4][4];
                ldsm4(phi + swz(row0 + rA, kt * 16 + cA), ph);
                ldsm4(plo + swz(row0 + rA, kt * 16 + cA), pl);
#pragma unroll
                for (int dq = 0; dq < 4; dq++) {
                    int dp = half * 4 + dq;
                    ldsm4t(kvh + swz(16 * kt + rA, 16 * dp + cA), vh[dq]);
                    ldsm4t(kvl + swz(16 * kt + rA, 16 * dp + cA), vl[dq]);
                }
#pragma unroll
                for (int dq = 0; dq < 4; dq++) {
                    mma16816(o[2 * dq],     ph, vh[dq][0], vh[dq][1]);
                    mma16816(o[2 * dq + 1], ph, vh[dq][2], vh[dq][3]);
                }
#pragma unroll
                for (int dq = 0; dq < 4; dq++) {
                    mma16816(o[2 * dq],     ph, vl[dq][0], vl[dq][1]);
                    mma16816(o[2 * dq + 1], ph, vl[dq][2], vl[dq][3]);
                }
#pragma unroll
                for (int dq = 0; dq < 4; dq++) {
                    mma16816(o[2 * dq],     pl, vh[dq][0], vh[dq][1]);
                    mma16816(o[2 * dq + 1], pl, vh[dq][2], vh[dq][3]);
                }
            }
        }

        float lt0 = redl[r1] + redl[96 + r1];
        float lt1 = redl[r2] + redl[96 + r2];
        float i0 = 1.f / lt0, i1 = 1.f / lt1;
        float* d1 = (r1 < nc)
            ? out + (((size_t)b * L_ + idxs[r1]) * V_ + k) * D_ : nullptr;
        float* d2 = (r2 < nc)
            ? out + (((size_t)b * L_ + idxs[r2]) * V_ + k) * D_ : nullptr;
#pragma unroll
        for (int n = 0; n < 8; n++) {
            int col = half * 64 + n * 8 + colb;
            if (d1) *(float2*)(d1 + col) = make_float2(o[n][0] * i0, o[n][1] * i0);
            if (d2) *(float2*)(d2 + col) = make_float2(o[n][2] * i1, o[n][3] * i1);
        }
    }
}

extern "C" void kernel_launch(void* const* d_in, const int* in_sizes, int n_in,
                              void* d_out, int out_size) {
    (void)in_sizes; (void)n_in; (void)out_size;
    const float* query = (const float*)d_in[0];
    const float* key   = (const float*)d_in[1];
    const float* value = (const float*)d_in[2];
    const int*   label = (const int*)d_in[3];
    float* out = (float*)d_out;

    split_kernel<<<4096, 256>>>((const float4*)query, (const float4*)value);
    sumk_kernel<<<B_ * L_, 256>>>((const float4*)key);
    build_idx_kernel<<<dim3(NC_, B_), 32>>>(label);
    cudaFuncSetAttribute(attn_mma_kernel,
                         cudaFuncAttributeMaxDynamicSharedMemorySize, SMEM_TOTAL);
    attn_mma_kernel<<<dim3(V_, 16, 1), 256, SMEM_TOTAL>>>(query, value, out);
}

// round 9
// speedup vs baseline: 3.0178x; 1.1396x over previous
#include <cuda_runtime.h>
#include <cuda_fp16.h>
#include <cstdint>

#define B_ 2
#define L_ 512
#define V_ 64
#define D_ 128
#define NC_ 8
#define NR_MAX 96

// ---- static device scratch (no allocations allowed) ----
__device__ float  g_sumK[B_ * L_ * D_];
__device__ __half g_sKh[B_ * L_ * D_];
__device__ __half g_sKl[B_ * L_ * D_];
__device__ __half g_Qh[B_ * L_ * V_ * D_];
__device__ __half g_Ql[B_ * L_ * V_ * D_];
__device__ __half g_Vh[B_ * L_ * V_ * D_];
__device__ __half g_Vl[B_ * L_ * V_ * D_];
__device__ int    g_idx[B_][NC_][L_];
__device__ int    g_cnt[B_][NC_];

#define SCALE_ 0.08838834764831845f

__device__ __forceinline__ uint32_t packh2(float a, float b2) {
    __half2 h = __halves2half2(__float2half_rn(a), __float2half_rn(b2));
    return *reinterpret_cast<uint32_t*>(&h);
}

// ===========================================================================
// Fused prep kernel: blocks [0,4096) split Q/V; [4096,5120) sumK; [5120,5136) idx
// ===========================================================================
__global__ void prep_kernel(const float4* __restrict__ q,
                            const float4* __restrict__ v,
                            const float4* __restrict__ key4,
                            const int* __restrict__ label) {
    __shared__ float4 part[256];
    const int blk = blockIdx.x;

    if (blk < 4096) {
        // ---- stream-split Q (scale folded) and V into fp16 hi/lo ----
        const int N4 = B_ * L_ * V_ * D_ / 4;
        bool isV = blk >= 2048;
        const float4* src = isV ? v : q;
        uint2* dh = (uint2*)(isV ? g_Vh : g_Qh);
        uint2* dl = (uint2*)(isV ? g_Vl : g_Ql);
        const float sc = isV ? 1.f : SCALE_;
        int base = (blk & 2047) * 256 + threadIdx.x;
#pragma unroll
        for (int u = 0; u < 4; u++) {
            int i = base + u * (N4 / 4);
            float4 x = src[i];
            x.x *= sc; x.y *= sc; x.z *= sc; x.w *= sc;
            __half hx = __float2half_rn(x.x), hy = __float2half_rn(x.y);
            __half hz = __float2half_rn(x.z), hw = __float2half_rn(x.w);
            uint2 hv, lv;
            { __half2 t = __halves2half2(hx, hy); hv.x = *(uint32_t*)&t; }
            { __half2 t = __halves2half2(hz, hw); hv.y = *(uint32_t*)&t; }
            lv.x = packh2(x.x - __half2float(hx), x.y - __half2float(hy));
            lv.y = packh2(x.z - __half2float(hz), x.w - __half2float(hw));
            dh[i] = hv; dl[i] = lv;
        }
    } else if (blk < 5120) {
        // ---- sumK = sum_v key (fp32 + fp16 hi/lo) ----
        int bl = blk - 4096;
        int g = threadIdx.x & 31, qd = threadIdx.x >> 5;
        const float4* p = key4 + (size_t)bl * (V_ * D_ / 4)
                        + (size_t)(qd * 8) * (D_ / 4) + g;
        float4 s = make_float4(0.f, 0.f, 0.f, 0.f);
#pragma unroll
        for (int vv = 0; vv < 8; vv++) {
            float4 t = p[(size_t)vv * (D_ / 4)];
            s.x += t.x; s.y += t.y; s.z += t.z; s.w += t.w;
        }
        part[threadIdx.x] = s;
        __syncthreads();
        if (qd < 4) {
            float4 a = part[threadIdx.x], b2 = part[threadIdx.x + 128];
            part[threadIdx.x] =
                make_float4(a.x + b2.x, a.y + b2.y, a.z + b2.z, a.w + b2.w);
        }
        __syncthreads();
        if (qd == 0) {
            float4 a = part[g], b2 = part[32 + g], c2 = part[64 + g], d2 = part[96 + g];
            float4 r = make_float4(a.x + b2.x + c2.x + d2.x, a.y + b2.y + c2.y + d2.y,
                                   a.z + b2.z + c2.z + d2.z, a.w + b2.w + c2.w + d2.w);
            ((float4*)g_sumK)[(size_t)bl * 32 + g] = r;
            __half hx = __float2half_rn(r.x), hy = __float2half_rn(r.y);
            __half hz = __float2half_rn(r.z), hw = __float2half_rn(r.w);
            size_t o = (size_t)bl * 64 + g * 2;
            { __half2 t = __halves2half2(hx, hy); ((uint32_t*)g_sKh)[o] = *(uint32_t*)&t; }
            { __half2 t = __halves2half2(hz, hw); ((uint32_t*)g_sKh)[o + 1] = *(uint32_t*)&t; }
            ((uint32_t*)g_sKl)[o] =
                packh2(r.x - __half2float(hx), r.y - __half2float(hy));
            ((uint32_t*)g_sKl)[o + 1] =
                packh2(r.z - __half2float(hz), r.w - __half2float(hw));
        }
    } else {
        // ---- deterministic per-(b,c) index lists via ballot compaction ----
        if (threadIdx.x >= 32) return;
        int bc = blk - 5120;
        int c = bc & 7, b = bc >> 3;
        int lane = threadIdx.x;
        int cnt = 0;
        for (int l0 = 0; l0 < L_; l0 += 32) {
            int l = l0 + lane;
            int lbl = label[b * L_ + l];
            unsigned m = __ballot_sync(0xffffffffu, lbl == c);
            if (lbl == c) {
                int pos = cnt + __popc(m & ((1u << lane) - 1u));
                g_idx[b][c][pos] = l;
            }
            cnt += __popc(m);
        }
        if (lane == 0) g_cnt[b][c] = cnt;
    }
}

// ===========================================================================
// PTX helpers (family-common, valid on target sm_103)
// ===========================================================================
__device__ __forceinline__ uint32_t smem_u32(const void* p) {
    uint32_t a;
    asm("{ .reg .u64 t; cvta.to.shared.u64 t, %1; cvt.u32.u64 %0, t; }"
        : "=r"(a) : "l"(p));
    return a;
}
__device__ __forceinline__ void cpa16(uint32_t dst, const void* src) {
    asm volatile("cp.async.cg.shared.global [%0], [%1], 16;"
                 :: "r"(dst), "l"(src));
}
__device__ __forceinline__ void ldsm4(uint32_t addr, uint32_t* r) {
    asm volatile("ldmatrix.sync.aligned.m8n8.x4.shared.b16 {%0,%1,%2,%3}, [%4];"
                 : "=r"(r[0]), "=r"(r[1]), "=r"(r[2]), "=r"(r[3]) : "r"(addr));
}
__device__ __forceinline__ void ldsm4t(uint32_t addr, uint32_t* r) {
    asm volatile("ldmatrix.sync.aligned.m8n8.x4.trans.shared.b16 {%0,%1,%2,%3}, [%4];"
                 : "=r"(r[0]), "=r"(r[1]), "=r"(r[2]), "=r"(r[3]) : "r"(addr));
}
__device__ __forceinline__ void mma16816(float* c, const uint32_t* a,
                                         uint32_t b0, uint32_t b1) {
    asm volatile(
        "mma.sync.aligned.m16n8k16.row.col.f32.f16.f16.f32 "
        "{%0,%1,%2,%3}, {%4,%5,%6,%7}, {%8,%9}, {%0,%1,%2,%3};"
        : "+f"(c[0]), "+f"(c[1]), "+f"(c[2]), "+f"(c[3])
        : "r"(a[0]), "r"(a[1]), "r"(a[2]), "r"(a[3]), "r"(b0), "r"(b1));
}
__device__ __forceinline__ void split2(float x0, float x1,
                                       uint32_t& hi, uint32_t& lo) {
    __half h0 = __float2half_rn(x0), h1 = __float2half_rn(x1);
    __half l0 = __float2half_rn(x0 - __half2float(h0));
    __half l1 = __float2half_rn(x1 - __half2float(h1));
    __half2 hp = __halves2half2(h0, h1), lp = __halves2half2(l0, l1);
    hi = *reinterpret_cast<uint32_t*>(&hp);
    lo = *reinterpret_cast<uint32_t*>(&lp);
}
// byte offset in an f16 tile (256B rows), 16B-chunk XOR swizzle
__device__ __forceinline__ uint32_t swz(int row, int col) {
    return (uint32_t)(row * 256) + (uint32_t)((((col >> 3) ^ (row & 7)) & 15) << 4)
         + (uint32_t)((col & 7) << 1);
}
__device__ __forceinline__ uint32_t swz16(int row, int ch) {
    return (uint32_t)(row * 256) + (uint32_t)(((ch ^ (row & 7)) & 15) << 4);
}

// smem layout: P tiles 48 rows; K/V tiles 96 rows (K becomes V)
#define SM_PHI  0
#define SM_PLO  12288
#define SM_KVHI 24576
#define SM_KVLO 49152
#define SM_IDX  73728    /* 96 ints */
#define SM_ORD  74112
#define SM_RED  74240    /* redm[2][48], redl[2][48] */
#define SMEM_TOTAL 75008

// Dead-code-in-practice fallback for nc > 96 (slow, simple, correct).
__device__ __noinline__ void attn_fallback(int b, int c, int k, int nc,
                                           const int* idxs,
                                           const float* query,
                                           const float* value,
                                           float* out) {
    for (int r = threadIdx.x; r < nc; r += blockDim.x) {
        int i = idxs[r];
        const float* q = query + (((size_t)b * L_ + i) * V_ + k) * D_;
        float m = -1e30f;
        for (int jj = 0; jj < nc; jj++) {
            const float* kr = g_sumK + ((size_t)b * L_ + idxs[jj]) * D_;
            float s = 0.f;
            for (int d = 0; d < D_; d++) s += q[d] * kr[d];
            m = fmaxf(m, s * SCALE_);
        }
        float l = 0.f;
        for (int jj = 0; jj < nc; jj++) {
            const float* kr = g_sumK + ((size_t)b * L_ + idxs[jj]) * D_;
            float s = 0.f;
            for (int d = 0; d < D_; d++) s += q[d] * kr[d];
            l += __expf(s * SCALE_ - m);
        }
        for (int d0 = 0; d0 < D_; d0 += 32) {
            float acc[32];
            for (int e = 0; e < 32; e++) acc[e] = 0.f;
            for (int jj = 0; jj < nc; jj++) {
                const float* kr = g_sumK + ((size_t)b * L_ + idxs[jj]) * D_;
                float s = 0.f;
                for (int d = 0; d < D_; d++) s += q[d] * kr[d];
                float p = __expf(s * SCALE_ - m) / l;
                const float* vr = value +
                    (((size_t)b * L_ + idxs[jj]) * V_ + k) * D_ + d0;
                for (int e = 0; e < 32; e++) acc[e] += p * vr[e];
            }
            float* dst = out + (((size_t)b * L_ + i) * V_ + k) * D_ + d0;
            for (int e = 0; e < 32; e++) dst[e] = acc[e];
        }
    }
}

// ===========================================================================
// HMMA clustered attention: CTA = (head, cluster-rank, row-half of 48).
// 192 threads = 6 warps = 3 strips x 2 halves. 3 CTAs/SM.
// ===========================================================================
extern __shared__ char smx[];

__global__ void __launch_bounds__(192, 3)
attn_mma_kernel(const float* __restrict__ query,
                const float* __restrict__ value,
                float* __restrict__ out) {
    const int k = blockIdx.x, cl = blockIdx.y, z = blockIdx.z;
    const int tid = threadIdx.x;
    const int lane = tid & 31;
    const int w = tid >> 5;          // 0..5
    const int half = w & 1;
    const int sid = w >> 1;          // strip 0..2

    // ---- LPT: rank clusters by descending count (deterministic tie-break)
    if (w == 0) {
        int key = -1;
        if (lane < 16) key = (g_cnt[lane >> 3][lane & 7] << 4) | (15 - lane);
        int rank = 0;
#pragma unroll
        for (int j = 0; j < 16; j++) {
            int other = __shfl_sync(0xffffffffu, key, j);
            if (lane < 16 && other > key) rank++;
        }
        if (lane < 16 && rank == cl) *(int*)(smx + SM_ORD) = lane;
    }
    __syncthreads();
    const int ordv = *(int*)(smx + SM_ORD);
    const int b = ordv >> 3, c = ordv & 7;

    const int nc = g_cnt[b][c];
    if (nc == 0) return;
    if (nc > NR_MAX) {
        if (z == 0) attn_fallback(b, c, k, nc, g_idx[b][c], query, value, out);
        return;
    }
    const int rowbase = z * 48;
    int nloc = nc - rowbase;
    if (nloc <= 0) return;
    if (nloc > 48) nloc = 48;

    int* idxs = (int*)(smx + SM_IDX);
    for (int t = tid; t < nc; t += 192) idxs[t] = g_idx[b][c][t];
    __syncthreads();

    const int nr = (nc + 15) & ~15;           // K/V rows, <= 96
    const int npair = nr >> 4;                // <= 6

    const uint32_t sb  = smem_u32(smx);
    const uint32_t phi = sb + SM_PHI, plo = sb + SM_PLO;
    const uint32_t kvh = sb + SM_KVHI, kvl = sb + SM_KVLO;

    // ---- async fill: Q rows [rowbase, rowbase+48) and K (all nr rows) ----
    for (int t = tid; t < 48 * 16; t += 192) {
        int lr = t >> 4, ch = t & 15;
        int gr = rowbase + lr;
        uint32_t so = swz16(lr, ch);
        if (gr < nc) {
            size_t qb = ((((size_t)b * L_ + idxs[gr]) * V_ + k) << 8) + (ch << 4);
            cpa16(phi + so, (const char*)g_Qh + qb);
            cpa16(plo + so, (const char*)g_Ql + qb);
        } else {
            uint4 zz = make_uint4(0, 0, 0, 0);
            *(uint4*)(smx + SM_PHI + so) = zz;
            *(uint4*)(smx + SM_PLO + so) = zz;
        }
    }
    for (int t = tid; t < nr * 16; t += 192) {
        int row = t >> 4, ch = t & 15;
        uint32_t so = swz16(row, ch);
        if (row < nc) {
            size_t kb = (((size_t)b * L_ + idxs[row]) << 8) + (ch << 4);
            cpa16(kvh + so, (const char*)g_sKh + kb);
            cpa16(kvl + so, (const char*)g_sKl + kb);
        } else {
            uint4 zz = make_uint4(0, 0, 0, 0);
            *(uint4*)(smx + SM_KVHI + so) = zz;
            *(uint4*)(smx + SM_KVLO + so) = zz;
        }
    }
    asm volatile("cp.async.commit_group;");
    asm volatile("cp.async.wait_group 0;" ::: "memory");
    __syncthreads();

    float* redm = (float*)(smx + SM_RED);     // [2][48]
    float* redl = redm + 96;

    const int g  = lane >> 3;
    const int rA = (lane & 7) + ((g & 1) << 3);
    const int cA = ((g >> 1) & 1) << 3;
    const int rB = (lane & 7) + (((g >> 1) & 1) << 3);
    const int cB = (g & 1) << 3;
    const int colb = (lane & 3) << 1;
    const int qr = lane >> 2;

    const int lr0 = sid * 16;
    const bool active = lr0 < nloc;
    const int r1 = lr0 + qr, r2 = r1 + 8;     // local P rows

    // ================= S = Q * Ksum^T ====================
    float cS[6][4];
#pragma unroll
    for (int n = 0; n < 6; n++)
#pragma unroll
        for (int r = 0; r < 4; r++) cS[n][r] = 0.f;

    if (active) {
#pragma unroll
        for (int s = 0; s < 8; s++) {
            uint32_t ah[4], al[4], bh[3][4], bl[3][4];
            ldsm4(phi + swz(lr0 + rA, s * 16 + cA), ah);
            ldsm4(plo + swz(lr0 + rA, s * 16 + cA), al);
#pragma unroll
            for (int u = 0; u < 3; u++) {
                int ti = half + 2 * u;
                if (ti < npair) {
                    ldsm4(kvh + swz(16 * ti + rB, s * 16 + cB), bh[u]);
                    ldsm4(kvl + swz(16 * ti + rB, s * 16 + cB), bl[u]);
                }
            }
            // term-major: same-accumulator distance = 6 mmas
#pragma unroll
            for (int u = 0; u < 3; u++)
                if (half + 2 * u < npair) {
                    mma16816(cS[2 * u],     ah, bh[u][0], bh[u][1]);
                    mma16816(cS[2 * u + 1], ah, bh[u][2], bh[u][3]);
                }
#pragma unroll
            for (int u = 0; u < 3; u++)
                if (half + 2 * u < npair) {
                    mma16816(cS[2 * u],     ah, bl[u][0], bl[u][1]);
                    mma16816(cS[2 * u + 1], ah, bl[u][2], bl[u][3]);
                }
#pragma unroll
            for (int u = 0; u < 3; u++)
                if (half + 2 * u < npair) {
                    mma16816(cS[2 * u],     al, bh[u][0], bh[u][1]);
                    mma16816(cS[2 * u + 1], al, bh[u][2], bh[u][3]);
                }
        }

        // partial row max
        float m0 = -1e30f, m1 = -1e30f;
#pragma unroll
        for (int u = 0; u < 3; u++) {
            int ti = half + 2 * u;
            if (ti < npair) {
#pragma unroll
                for (int sub = 0; sub < 2; sub++) {
                    int n = 2 * u + sub;
                    int c0 = ti * 16 + sub * 8 + colb;
                    if (c0 < nc)     { m0 = fmaxf(m0, cS[n][0]); m1 = fmaxf(m1, cS[n][2]); }
                    if (c0 + 1 < nc) { m0 = fmaxf(m0, cS[n][1]); m1 = fmaxf(m1, cS[n][3]); }
                }
            }
        }
        m0 = fmaxf(m0, __shfl_xor_sync(0xffffffffu, m0, 1));
        m0 = fmaxf(m0, __shfl_xor_sync(0xffffffffu, m0, 2));
        m1 = fmaxf(m1, __shfl_xor_sync(0xffffffffu, m1, 1));
        m1 = fmaxf(m1, __shfl_xor_sync(0xffffffffu, m1, 2));
        if ((lane & 3) == 0) {
            redm[half * 48 + r1] = m0;
            redm[half * 48 + r2] = m1;
        }
    }
    __syncthreads();   // all K ldsm done + partial maxes visible

    // ---- early V issue (K tiles dead); copy proceeds under softmax -------
    for (int t = tid; t < nr * 16; t += 192) {
        int row = t >> 4, ch = t & 15;
        uint32_t so = swz16(row, ch);
        if (row < nc) {
            size_t vb = ((((size_t)b * L_ + idxs[row]) * V_ + k) << 8) + (ch << 4);
            cpa16(kvh + so, (const char*)g_Vh + vb);
            cpa16(kvl + so, (const char*)g_Vl + vb);
        } else {
            uint4 zz = make_uint4(0, 0, 0, 0);
            *(uint4*)(smx + SM_KVHI + so) = zz;
            *(uint4*)(smx + SM_KVLO + so) = zz;
        }
    }
    asm volatile("cp.async.commit_group;");

    // ---- softmax: exp, P -> smem (over Q tiles), partial l ---------------
    if (active) {
        float mt0 = fmaxf(redm[r1], redm[48 + r1]);
        float mt1 = fmaxf(redm[r2], redm[48 + r2]);
        float l0 = 0.f, l1 = 0.f;
#pragma unroll
        for (int u = 0; u < 3; u++) {
            int ti = half + 2 * u;
            if (ti < npair) {
#pragma unroll
                for (int sub = 0; sub < 2; sub++) {
                    int n = 2 * u + sub;
                    int c0 = ti * 16 + sub * 8 + colb;
                    float p0 = (c0     < nc) ? __expf(cS[n][0] - mt0) : 0.f;
                    float p1 = (c0 + 1 < nc) ? __expf(cS[n][1] - mt0) : 0.f;
                    float p2 = (c0     < nc) ? __expf(cS[n][2] - mt1) : 0.f;
                    float p3 = (c0 + 1 < nc) ? __expf(cS[n][3] - mt1) : 0.f;
                    l0 += p0 + p1; l1 += p2 + p3;
                    uint32_t hi, lo;
                    split2(p0, p1, hi, lo);
                    *(uint32_t*)(smx + SM_PHI + swz(r1, c0)) = hi;
                    *(uint32_t*)(smx + SM_PLO + swz(r1, c0)) = lo;
                    split2(p2, p3, hi, lo);
                    *(uint32_t*)(smx + SM_PHI + swz(r2, c0)) = hi;
                    *(uint32_t*)(smx + SM_PLO + swz(r2, c0)) = lo;
                }
            }
        }
        l0 += __shfl_xor_sync(0xffffffffu, l0, 1);
        l0 += __shfl_xor_sync(0xffffffffu, l0, 2);
        l1 += __shfl_xor_sync(0xffffffffu, l1, 1);
        l1 += __shfl_xor_sync(0xffffffffu, l1, 2);
        if ((lane & 3) == 0) {
            redl[half * 48 + r1] = l0;
            redl[half * 48 + r2] = l1;
        }
    }
    asm volatile("cp.async.wait_group 0;" ::: "memory");
    __syncthreads();   // V tiles + P tiles + partial l complete

    // ================= O = P * V  (d-range = half*64 .. +63) ===============
    if (active) {
        float o[8][4];
#pragma unroll
        for (int n = 0; n < 8; n++)
#pragma unroll
            for (int r = 0; r < 4; r++) o[n][r] = 0.f;

#pragma unroll
        for (int kt = 0; kt < 6; kt++) {
            if (kt < npair) {
                uint32_t ph[4], pl[4], vh[4][4], vl[4][4];
                ldsm4(phi + swz(lr0 + rA, kt * 16 + cA), ph);
                ldsm4(plo + swz(lr0 + rA, kt * 16 + cA), pl);
#pragma unroll
                for (int dq = 0; dq < 4; dq++) {
                    int dp = half * 4 + dq;
                    ldsm4t(kvh + swz(16 * kt + rA, 16 * dp + cA), vh[dq]);
                    ldsm4t(kvl + swz(16 * kt + rA, 16 * dp + cA), vl[dq]);
                }
#pragma unroll
                for (int dq = 0; dq < 4; dq++) {
                    mma16816(o[2 * dq],     ph, vh[dq][0], vh[dq][1]);
                    mma16816(o[2 * dq + 1], ph, vh[dq][2], vh[dq][3]);
                }
#pragma unroll
                for (int dq = 0; dq < 4; dq++) {
                    mma16816(o[2 * dq],     ph, vl[dq][0], vl[dq][1]);
                    mma16816(o[2 * dq + 1], ph, vl[dq][2], vl[dq][3]);
                }
#pragma unroll
                for (int dq = 0; dq < 4; dq++) {
                    mma16816(o[2 * dq],     pl, vh[dq][0], vh[dq][1]);
                    mma16816(o[2 * dq + 1], pl, vh[dq][2], vh[dq][3]);
                }
            }
        }

        // ---- epilogue
        float lt0 = redl[r1] + redl[48 + r1];
        float lt1 = redl[r2] + redl[48 + r2];
        float i0 = 1.f / lt0, i1 = 1.f / lt1;
        int gr1 = rowbase + r1, gr2 = rowbase + r2;
        float* d1 = (gr1 < nc)
            ? out + (((size_t)b * L_ + idxs[gr1]) * V_ + k) * D_ : nullptr;
        float* d2 = (gr2 < nc)
            ? out + (((size_t)b * L_ + idxs[gr2]) * V_ + k) * D_ : nullptr;
#pragma unroll
        for (int n = 0; n < 8; n++) {
            int col = half * 64 + (n >> 1) * 16 + (n & 1) * 8 + colb;
            if (d1) *(float2*)(d1 + col) = make_float2(o[n][0] * i0, o[n][1] * i0);
            if (d2) *(float2*)(d2 + col) = make_float2(o[n][2] * i1, o[n][3] * i1);
        }
    }
}

extern "C" void kernel_launch(void* const* d_in, const int* in_sizes, int n_in,
                              void* d_out, int out_size) {
    (void)in_sizes; (void)n_in; (void)out_size;
    const float* query = (const float*)d_in[0];
    const float* key   = (const float*)d_in[1];
    const float* value = (const float*)d_in[2];
    const int*   label = (const int*)d_in[3];
    float* out = (float*)d_out;

    prep_kernel<<<5136, 256>>>((const float4*)query, (const float4*)value,
                               (const float4*)key, label);
    cudaFuncSetAttribute(attn_mma_kernel,
                         cudaFuncAttributeMaxDynamicSharedMemorySize, SMEM_TOTAL);
    attn_mma_kernel<<<dim3(V_, 16, 2), 192, SMEM_TOTAL>>>(query, value, out);
}

// round 10
// speedup vs baseline: 3.0540x; 1.0120x over previous
#include <cuda_runtime.h>
#include <cuda_fp16.h>
#include <cstdint>

#define B_ 2
#define L_ 512
#define V_ 64
#define D_ 128
#define NC_ 8
#define NR_MAX 96

// ---- static device scratch (no allocations allowed) ----
__device__ float  g_sumK[B_ * L_ * D_];
__device__ __half g_sKh[B_ * L_ * D_];
__device__ __half g_sKl[B_ * L_ * D_];
__device__ int    g_idx[B_][NC_][L_];
__device__ int    g_cnt[B_][NC_];

#define SCALE_ 0.08838834764831845f

__device__ __forceinline__ uint32_t packh2(float a, float b2) {
    __half2 h = __halves2half2(__float2half_rn(a), __float2half_rn(b2));
    return *reinterpret_cast<uint32_t*>(&h);
}

// ===========================================================================
// Prep kernel: blocks [0,1024) sumK (+fp16 hi/lo); [1024,1040) idx lists
// ===========================================================================
__global__ void prep_kernel(const float4* __restrict__ key4,
                            const int* __restrict__ label) {
    __shared__ float4 part[256];
    const int blk = blockIdx.x;

    if (blk < 1024) {
        int bl = blk;
        int g = threadIdx.x & 31, qd = threadIdx.x >> 5;
        const float4* p = key4 + (size_t)bl * (V_ * D_ / 4)
                        + (size_t)(qd * 8) * (D_ / 4) + g;
        float4 s = make_float4(0.f, 0.f, 0.f, 0.f);
#pragma unroll
        for (int vv = 0; vv < 8; vv++) {
            float4 t = p[(size_t)vv * (D_ / 4)];
            s.x += t.x; s.y += t.y; s.z += t.z; s.w += t.w;
        }
        part[threadIdx.x] = s;
        __syncthreads();
        if (qd < 4) {
            float4 a = part[threadIdx.x], b2 = part[threadIdx.x + 128];
            part[threadIdx.x] =
                make_float4(a.x + b2.x, a.y + b2.y, a.z + b2.z, a.w + b2.w);
        }
        __syncthreads();
        if (qd == 0) {
            float4 a = part[g], b2 = part[32 + g], c2 = part[64 + g], d2 = part[96 + g];
            float4 r = make_float4(a.x + b2.x + c2.x + d2.x, a.y + b2.y + c2.y + d2.y,
                                   a.z + b2.z + c2.z + d2.z, a.w + b2.w + c2.w + d2.w);
            ((float4*)g_sumK)[(size_t)bl * 32 + g] = r;
            __half hx = __float2half_rn(r.x), hy = __float2half_rn(r.y);
            __half hz = __float2half_rn(r.z), hw = __float2half_rn(r.w);
            size_t o = (size_t)bl * 64 + g * 2;
            { __half2 t = __halves2half2(hx, hy); ((uint32_t*)g_sKh)[o] = *(uint32_t*)&t; }
            { __half2 t = __halves2half2(hz, hw); ((uint32_t*)g_sKh)[o + 1] = *(uint32_t*)&t; }
            ((uint32_t*)g_sKl)[o] =
                packh2(r.x - __half2float(hx), r.y - __half2float(hy));
            ((uint32_t*)g_sKl)[o + 1] =
                packh2(r.z - __half2float(hz), r.w - __half2float(hw));
        }
    } else {
        if (threadIdx.x >= 32) return;
        int bc = blk - 1024;
        int c = bc & 7, b = bc >> 3;
        int lane = threadIdx.x;
        int cnt = 0;
        for (int l0 = 0; l0 < L_; l0 += 32) {
            int l = l0 + lane;
            int lbl = label[b * L_ + l];
            unsigned m = __ballot_sync(0xffffffffu, lbl == c);
            if (lbl == c) {
                int pos = cnt + __popc(m & ((1u << lane) - 1u));
                g_idx[b][c][pos] = l;
            }
            cnt += __popc(m);
        }
        if (lane == 0) g_cnt[b][c] = cnt;
    }
}

// ===========================================================================
// PTX helpers (family-common, valid on target sm_103)
// ===========================================================================
__device__ __forceinline__ uint32_t smem_u32(const void* p) {
    uint32_t a;
    asm("{ .reg .u64 t; cvta.to.shared.u64 t, %1; cvt.u32.u64 %0, t; }"
        : "=r"(a) : "l"(p));
    return a;
}
__device__ __forceinline__ void cpa16(uint32_t dst, const void* src) {
    asm volatile("cp.async.cg.shared.global [%0], [%1], 16;"
                 :: "r"(dst), "l"(src));
}
__device__ __forceinline__ void ldsm4(uint32_t addr, uint32_t* r) {
    asm volatile("ldmatrix.sync.aligned.m8n8.x4.shared.b16 {%0,%1,%2,%3}, [%4];"
                 : "=r"(r[0]), "=r"(r[1]), "=r"(r[2]), "=r"(r[3]) : "r"(addr));
}
__device__ __forceinline__ void ldsm4t(uint32_t addr, uint32_t* r) {
    asm volatile("ldmatrix.sync.aligned.m8n8.x4.trans.shared.b16 {%0,%1,%2,%3}, [%4];"
                 : "=r"(r[0]), "=r"(r[1]), "=r"(r[2]), "=r"(r[3]) : "r"(addr));
}
__device__ __forceinline__ void mma16816(float* c, const uint32_t* a,
                                         uint32_t b0, uint32_t b1) {
    asm volatile(
        "mma.sync.aligned.m16n8k16.row.col.f32.f16.f16.f32 "
        "{%0,%1,%2,%3}, {%4,%5,%6,%7}, {%8,%9}, {%0,%1,%2,%3};"
        : "+f"(c[0]), "+f"(c[1]), "+f"(c[2]), "+f"(c[3])
        : "r"(a[0]), "r"(a[1]), "r"(a[2]), "r"(a[3]), "r"(b0), "r"(b1));
}
__device__ __forceinline__ void split2(float x0, float x1,
                                       uint32_t& hi, uint32_t& lo) {
    __half h0 = __float2half_rn(x0), h1 = __float2half_rn(x1);
    __half l0 = __float2half_rn(x0 - __half2float(h0));
    __half l1 = __float2half_rn(x1 - __half2float(h1));
    __half2 hp = __halves2half2(h0, h1), lp = __halves2half2(l0, l1);
    hi = *reinterpret_cast<uint32_t*>(&hp);
    lo = *reinterpret_cast<uint32_t*>(&lp);
}
// byte offset in an f16 tile (256B rows), 16B-chunk XOR swizzle
__device__ __forceinline__ uint32_t swz(int row, int col) {
    return (uint32_t)(row * 256) + (uint32_t)((((col >> 3) ^ (row & 7)) & 15) << 4)
         + (uint32_t)((col & 7) << 1);
}
__device__ __forceinline__ uint32_t swz16(int row, int ch) {
    return (uint32_t)(row * 256) + (uint32_t)(((ch ^ (row & 7)) & 15) << 4);
}

// smem layout: P tiles 48 rows; K/V tiles 96 rows (K becomes V).
// fp32 staging: Q row r = [PHI+r*256 | PLO+r*256]; V row r = [KVHI+r*256 | KVLO+r*256]
#define SM_PHI  0
#define SM_PLO  12288
#define SM_KVHI 24576
#define SM_KVLO 49152
#define SM_IDX  73728    /* 96 ints */
#define SM_ORD  74112
#define SM_RED  74240    /* redm[2][48], redl[2][48] */
#define SMEM_TOTAL 75008

// Dead-code-in-practice fallback for nc > 96 (slow, simple, correct).
__device__ __noinline__ void attn_fallback(int b, int c, int k, int nc,
                                           const int* idxs,
                                           const float* query,
                                           const float* value,
                                           float* out) {
    for (int r = threadIdx.x; r < nc; r += blockDim.x) {
        int i = idxs[r];
        const float* q = query + (((size_t)b * L_ + i) * V_ + k) * D_;
        float m = -1e30f;
        for (int jj = 0; jj < nc; jj++) {
            const float* kr = g_sumK + ((size_t)b * L_ + idxs[jj]) * D_;
            float s = 0.f;
            for (int d = 0; d < D_; d++) s += q[d] * kr[d];
            m = fmaxf(m, s * SCALE_);
        }
        float l = 0.f;
        for (int jj = 0; jj < nc; jj++) {
            const float* kr = g_sumK + ((size_t)b * L_ + idxs[jj]) * D_;
            float s = 0.f;
            for (int d = 0; d < D_; d++) s += q[d] * kr[d];
            l += __expf(s * SCALE_ - m);
        }
        for (int d0 = 0; d0 < D_; d0 += 32) {
            float acc[32];
            for (int e = 0; e < 32; e++) acc[e] = 0.f;
            for (int jj = 0; jj < nc; jj++) {
                const float* kr = g_sumK + ((size_t)b * L_ + idxs[jj]) * D_;
                float s = 0.f;
                for (int d = 0; d < D_; d++) s += q[d] * kr[d];
                float p = __expf(s * SCALE_ - m) / l;
                const float* vr = value +
                    (((size_t)b * L_ + idxs[jj]) * V_ + k) * D_ + d0;
                for (int e = 0; e < 32; e++) acc[e] += p * vr[e];
            }
            float* dst = out + (((size_t)b * L_ + i) * V_ + k) * D_ + d0;
            for (int e = 0; e < 32; e++) dst[e] = acc[e];
        }
    }
}

// ===========================================================================
// HMMA clustered attention: CTA = (head, cluster-rank, row-half of 48).
// Raw fp32 Q/V via cp.async, smem->reg->smem split conversion in-kernel.
// ===========================================================================
extern __shared__ char smx[];

__global__ void __launch_bounds__(192, 3)
attn_mma_kernel(const float* __restrict__ query,
                const float* __restrict__ value,
                float* __restrict__ out) {
    const int k = blockIdx.x, cl = blockIdx.y, z = blockIdx.z;
    const int tid = threadIdx.x;
    const int lane = tid & 31;
    const int w = tid >> 5;          // 0..5
    const int half = w & 1;
    const int sid = w >> 1;          // strip 0..2

    // ---- LPT: rank clusters by descending count (deterministic tie-break)
    if (w == 0) {
        int key = -1;
        if (lane < 16) key = (g_cnt[lane >> 3][lane & 7] << 4) | (15 - lane);
        int rank = 0;
#pragma unroll
        for (int j = 0; j < 16; j++) {
            int other = __shfl_sync(0xffffffffu, key, j);
            if (lane < 16 && other > key) rank++;
        }
        if (lane < 16 && rank == cl) *(int*)(smx + SM_ORD) = lane;
    }
    __syncthreads();
    const int ordv = *(int*)(smx + SM_ORD);
    const int b = ordv >> 3, c = ordv & 7;

    const int nc = g_cnt[b][c];
    if (nc == 0) return;
    if (nc > NR_MAX) {
        if (z == 0) attn_fallback(b, c, k, nc, g_idx[b][c], query, value, out);
        return;
    }
    const int rowbase = z * 48;
    int nloc = nc - rowbase;
    if (nloc <= 0) return;
    if (nloc > 48) nloc = 48;

    int* idxs = (int*)(smx + SM_IDX);
    for (int t = tid; t < nc; t += 192) idxs[t] = g_idx[b][c][t];
    __syncthreads();

    const int nr = (nc + 15) & ~15;           // K/V rows, <= 96
    const int npair = nr >> 4;                // <= 6

    const uint32_t sb  = smem_u32(smx);
    const uint32_t phi = sb + SM_PHI, plo = sb + SM_PLO;
    const uint32_t kvh = sb + SM_KVHI, kvl = sb + SM_KVLO;

    // ---- async fill: raw fp32 Q rows -> P-region staging; K hi/lo -> KV ----
    for (int t = tid; t < 48 * 32; t += 192) {          // 1536 x 16B chunks
        int lr = t >> 5, ch = t & 31;
        int gr = rowbase + lr;
        if (gr < nc) {
            uint32_t dst = ((ch & 16) ? plo : phi) + lr * 256 + (ch & 15) * 16;
            size_t qb = ((((size_t)b * L_ + idxs[gr]) * V_ + k) << 9) + (ch << 4);
            cpa16(dst, (const char*)query + qb);
        }
    }
    for (int t = tid; t < nr * 16; t += 192) {
        int row = t >> 4, ch = t & 15;
        uint32_t so = swz16(row, ch);
        if (row < nc) {
            size_t kb = (((size_t)b * L_ + idxs[row]) << 8) + (ch << 4);
            cpa16(kvh + so, (const char*)g_sKh + kb);
            cpa16(kvl + so, (const char*)g_sKl + kb);
        } else {
            uint4 zz = make_uint4(0, 0, 0, 0);
            *(uint4*)(smx + SM_KVHI + so) = zz;
            *(uint4*)(smx + SM_KVLO + so) = zz;
        }
    }
    asm volatile("cp.async.commit_group;");
    asm volatile("cp.async.wait_group 0;" ::: "memory");
    __syncthreads();

    // ---- convert Q: staging -> regs -> split hi/lo (scale folded) --------
    {
        float2 vb[16];
#pragma unroll
        for (int i = 0; i < 16; i++) {
            int f = i * 192 + tid;                   // < 3072 float2
            int row = f >> 6, bo = (f & 63) * 8;
            int off = ((bo & 256) ? SM_PLO : SM_PHI) + row * 256 + (bo & 255);
            vb[i] = *(const float2*)(smx + off);
        }
        __syncthreads();
#pragma unroll
        for (int i = 0; i < 16; i++) {
            int f = i * 192 + tid;
            int row = f >> 6, col = (f & 63) * 2;
            uint32_t hi = 0, lo = 0;
            if (rowbase + row < nc)
                split2(vb[i].x * SCALE_, vb[i].y * SCALE_, hi, lo);
            *(uint32_t*)(smx + SM_PHI + swz(row, col)) = hi;
            *(uint32_t*)(smx + SM_PLO + swz(row, col)) = lo;
        }
    }
    __syncthreads();

    float* redm = (float*)(smx + SM_RED);     // [2][48]
    float* redl = redm + 96;

    const int g  = lane >> 3;
    const int rA = (lane & 7) + ((g & 1) << 3);
    const int cA = ((g >> 1) & 1) << 3;
    const int rB = (lane & 7) + (((g >> 1) & 1) << 3);
    const int cB = (g & 1) << 3;
    const int colb = (lane & 3) << 1;
    const int qr = lane >> 2;

    const int lr0 = sid * 16;
    const bool active = lr0 < nloc;
    const int r1 = lr0 + qr, r2 = r1 + 8;     // local P rows

    // ================= S = Q * Ksum^T ====================
    float cS[6][4];
#pragma unroll
    for (int n = 0; n < 6; n++)
#pragma unroll
        for (int r = 0; r < 4; r++) cS[n][r] = 0.f;

    if (active) {
#pragma unroll
        for (int s = 0; s < 8; s++) {
            uint32_t ah[4], al[4], bh[3][4], bl[3][4];
            ldsm4(phi + swz(lr0 + rA, s * 16 + cA), ah);
            ldsm4(plo + swz(lr0 + rA, s * 16 + cA), al);
#pragma unroll
            for (int u = 0; u < 3; u++) {
                int ti = half + 2 * u;
                if (ti < npair) {
                    ldsm4(kvh + swz(16 * ti + rB, s * 16 + cB), bh[u]);
                    ldsm4(kvl + swz(16 * ti + rB, s * 16 + cB), bl[u]);
                }
            }
#pragma unroll
            for (int u = 0; u < 3; u++)
                if (half + 2 * u < npair) {
                    mma16816(cS[2 * u],     ah, bh[u][0], bh[u][1]);
                    mma16816(cS[2 * u + 1], ah, bh[u][2], bh[u][3]);
                }
#pragma unroll
            for (int u = 0; u < 3; u++)
                if (half + 2 * u < npair) {
                    mma16816(cS[2 * u],     ah, bl[u][0], bl[u][1]);
                    mma16816(cS[2 * u + 1], ah, bl[u][2], bl[u][3]);
                }
#pragma unroll
            for (int u = 0; u < 3; u++)
                if (half + 2 * u < npair) {
                    mma16816(cS[2 * u],     al, bh[u][0], bh[u][1]);
                    mma16816(cS[2 * u + 1], al, bh[u][2], bh[u][3]);
                }
        }

        float m0 = -1e30f, m1 = -1e30f;
#pragma unroll
        for (int u = 0; u < 3; u++) {
            int ti = half + 2 * u;
            if (ti < npair) {
#pragma unroll
                for (int sub = 0; sub < 2; sub++) {
                    int n = 2 * u + sub;
                    int c0 = ti * 16 + sub * 8 + colb;
                    if (c0 < nc)     { m0 = fmaxf(m0, cS[n][0]); m1 = fmaxf(m1, cS[n][2]); }
                    if (c0 + 1 < nc) { m0 = fmaxf(m0, cS[n][1]); m1 = fmaxf(m1, cS[n][3]); }
                }
            }
        }
        m0 = fmaxf(m0, __shfl_xor_sync(0xffffffffu, m0, 1));
        m0 = fmaxf(m0, __shfl_xor_sync(0xffffffffu, m0, 2));
        m1 = fmaxf(m1, __shfl_xor_sync(0xffffffffu, m1, 1));
        m1 = fmaxf(m1, __shfl_xor_sync(0xffffffffu, m1, 2));
        if ((lane & 3) == 0) {
            redm[half * 48 + r1] = m0;
            redm[half * 48 + r2] = m1;
        }
    }
    __syncthreads();   // all K ldsm done + partial maxes visible

    // ---- early raw-fp32 V issue into KV staging (K dead) -----------------
    for (int t = tid; t < nr * 32; t += 192) {          // up to 3072 chunks
        int row = t >> 5, ch = t & 31;
        if (row < nc) {
            uint32_t dst = ((ch & 16) ? kvl : kvh) + row * 256 + (ch & 15) * 16;
            size_t vb2 = ((((size_t)b * L_ + idxs[row]) * V_ + k) << 9) + (ch << 4);
            cpa16(dst, (const char*)value + vb2);
        }
    }
    asm volatile("cp.async.commit_group;");

    // ---- softmax: exp, P -> smem (over Q tiles), partial l ---------------
    if (active) {
        float mt0 = fmaxf(redm[r1], redm[48 + r1]);
        float mt1 = fmaxf(redm[r2], redm[48 + r2]);
        float l0 = 0.f, l1 = 0.f;
#pragma unroll
        for (int u = 0; u < 3; u++) {
            int ti = half + 2 * u;
            if (ti < npair) {
#pragma unroll
                for (int sub = 0; sub < 2; sub++) {
                    int n = 2 * u + sub;
                    int c0 = ti * 16 + sub * 8 + colb;
                    float p0 = (c0     < nc) ? __expf(cS[n][0] - mt0) : 0.f;
                    float p1 = (c0 + 1 < nc) ? __expf(cS[n][1] - mt0) : 0.f;
                    float p2 = (c0     < nc) ? __expf(cS[n][2] - mt1) : 0.f;
                    float p3 = (c0 + 1 < nc) ? __expf(cS[n][3] - mt1) : 0.f;
                    l0 += p0 + p1; l1 += p2 + p3;
                    uint32_t hi, lo;
                    split2(p0, p1, hi, lo);
                    *(uint32_t*)(smx + SM_PHI + swz(r1, c0)) = hi;
                    *(uint32_t*)(smx + SM_PLO + swz(r1, c0)) = lo;
                    split2(p2, p3, hi, lo);
                    *(uint32_t*)(smx + SM_PHI + swz(r2, c0)) = hi;
                    *(uint32_t*)(smx + SM_PLO + swz(r2, c0)) = lo;
                }
            }
        }
        l0 += __shfl_xor_sync(0xffffffffu, l0, 1);
        l0 += __shfl_xor_sync(0xffffffffu, l0, 2);
        l1 += __shfl_xor_sync(0xffffffffu, l1, 1);
        l1 += __shfl_xor_sync(0xffffffffu, l1, 2);
        if ((lane & 3) == 0) {
            redl[half * 48 + r1] = l0;
            redl[half * 48 + r2] = l1;
        }
    }
    asm volatile("cp.async.wait_group 0;" ::: "memory");
    __syncthreads();   // V staging + P tiles + partial l complete

    // ---- convert V: two 48-row passes, reg-buffered (disjoint regions) ---
    {
#pragma unroll 1
        for (int pass = 0; pass < 2; pass++) {
            if (pass == 1 && nr <= 48) break;
            float2 vb[16];
#pragma unroll
            for (int i = 0; i < 16; i++) {
                int f = i * 192 + tid;
                int row = pass * 48 + (f >> 6), bo = (f & 63) * 8;
                int off = ((bo & 256) ? SM_KVLO : SM_KVHI) + row * 256 + (bo & 255);
                vb[i] = *(const float2*)(smx + off);
            }
            __syncthreads();
#pragma unroll
            for (int i = 0; i < 16; i++) {
                int f = i * 192 + tid;
                int row = pass * 48 + (f >> 6), col = (f & 63) * 2;
                uint32_t hi = 0, lo = 0;
                if (row < nc) split2(vb[i].x, vb[i].y, hi, lo);
                *(uint32_t*)(smx + SM_KVHI + swz(row, col)) = hi;
                *(uint32_t*)(smx + SM_KVLO + swz(row, col)) = lo;
            }
            __syncthreads();
        }
    }

    // ================= O = P * V  (d-range = half*64 .. +63) ===============
    if (active) {
        float o[8][4];
#pragma unroll
        for (int n = 0; n < 8; n++)
#pragma unroll
            for (int r = 0; r < 4; r++) o[n][r] = 0.f;

#pragma unroll
        for (int kt = 0; kt < 6; kt++) {
            if (kt < npair) {
                uint32_t ph[4], pl[4], vh[4][4], vl[4][4];
                ldsm4(phi + swz(lr0 + rA, kt * 16 + cA), ph);
                ldsm4(plo + swz(lr0 + rA, kt * 16 + cA), pl);
#pragma unroll
                for (int dq = 0; dq < 4; dq++) {
                    int dp = half * 4 + dq;
                    ldsm4t(kvh + swz(16 * kt + rA, 16 * dp + cA), vh[dq]);
                    ldsm4t(kvl + swz(16 * kt + rA, 16 * dp + cA), vl[dq]);
                }
#pragma unroll
                for (int dq = 0; dq < 4; dq++) {
                    mma16816(o[2 * dq],     ph, vh[dq][0], vh[dq][1]);
                    mma16816(o[2 * dq + 1], ph, vh[dq][2], vh[dq][3]);
                }
#pragma unroll
                for (int dq = 0; dq < 4; dq++) {
                    mma16816(o[2 * dq],     ph, vl[dq][0], vl[dq][1]);
                    mma16816(o[2 * dq + 1], ph, vl[dq][2], vl[dq][3]);
                }
#pragma unroll
                for (int dq = 0; dq < 4; dq++) {
                    mma16816(o[2 * dq],     pl, vh[dq][0], vh[dq][1]);
                    mma16816(o[2 * dq + 1], pl, vh[dq][2], vh[dq][3]);
                }
            }
        }

        // ---- epilogue
        float lt0 = redl[r1] + redl[48 + r1];
        float lt1 = redl[r2] + redl[48 + r2];
        float i0 = 1.f / lt0, i1 = 1.f / lt1;
        int gr1 = rowbase + r1, gr2 = rowbase + r2;
        float* d1 = (gr1 < nc)
            ? out + (((size_t)b * L_ + idxs[gr1]) * V_ + k) * D_ : nullptr;
        float* d2 = (gr2 < nc)
            ? out + (((size_t)b * L_ + idxs[gr2]) * V_ + k) * D_ : nullptr;
#pragma unroll
        for (int n = 0; n < 8; n++) {
            int col = half * 64 + (n >> 1) * 16 + (n & 1) * 8 + colb;
            if (d1) *(float2*)(d1 + col) = make_float2(o[n][0] * i0, o[n][1] * i0);
            if (d2) *(float2*)(d2 + col) = make_float2(o[n][2] * i1, o[n][3] * i1);
        }
    }
}

extern "C" void kernel_launch(void* const* d_in, const int* in_sizes, int n_in,
                              void* d_out, int out_size) {
    (void)in_sizes; (void)n_in; (void)out_size;
    const float* query = (const float*)d_in[0];
    const float* key   = (const float*)d_in[1];
    const float* value = (const float*)d_in[2];
    const int*   label = (const int*)d_in[3];
    float* out = (float*)d_out;

    prep_kernel<<<1040, 256>>>((const float4*)key, label);
    cudaFuncSetAttribute(attn_mma_kernel,
                         cudaFuncAttributeMaxDynamicSharedMemorySize, SMEM_TOTAL);
    attn_mma_kernel<<<dim3(V_, 16, 2), 192, SMEM_TOTAL>>>(query, value, out);
}

// round 11
// speedup vs baseline: 3.2174x; 1.0535x over previous
#include <cuda_runtime.h>
#include <cuda_fp16.h>
#include <cstdint>

#define B_ 2
#define L_ 512
#define V_ 64
#define D_ 128
#define NC_ 8
#define NR_MAX 96

// ---- static device scratch (no allocations allowed) ----
__device__ float  g_sumK[B_ * L_ * D_];
__device__ __half g_sKh[B_ * L_ * D_];
__device__ __half g_sKl[B_ * L_ * D_];
__device__ int    g_idx[B_][NC_][L_];
__device__ int    g_cnt[B_][NC_];

#define SCALE_ 0.08838834764831845f

__device__ __forceinline__ uint32_t packh2(float a, float b2) {
    __half2 h = __halves2half2(__float2half_rn(a), __float2half_rn(b2));
    return *reinterpret_cast<uint32_t*>(&h);
}

// ===========================================================================
// Prep kernel: blocks [0,1024) sumK (+fp16 hi/lo); [1024,1040) idx lists
// ===========================================================================
__global__ void prep_kernel(const float4* __restrict__ key4,
                            const int* __restrict__ label) {
    __shared__ float4 part[256];
    const int blk = blockIdx.x;

    if (blk < 1024) {
        int bl = blk;
        int g = threadIdx.x & 31, qd = threadIdx.x >> 5;
        const float4* p = key4 + (size_t)bl * (V_ * D_ / 4)
                        + (size_t)(qd * 8) * (D_ / 4) + g;
        float4 s = make_float4(0.f, 0.f, 0.f, 0.f);
#pragma unroll
        for (int vv = 0; vv < 8; vv++) {
            float4 t = p[(size_t)vv * (D_ / 4)];
            s.x += t.x; s.y += t.y; s.z += t.z; s.w += t.w;
        }
        part[threadIdx.x] = s;
        __syncthreads();
        if (qd < 4) {
            float4 a = part[threadIdx.x], b2 = part[threadIdx.x + 128];
            part[threadIdx.x] =
                make_float4(a.x + b2.x, a.y + b2.y, a.z + b2.z, a.w + b2.w);
        }
        __syncthreads();
        if (qd == 0) {
            float4 a = part[g], b2 = part[32 + g], c2 = part[64 + g], d2 = part[96 + g];
            float4 r = make_float4(a.x + b2.x + c2.x + d2.x, a.y + b2.y + c2.y + d2.y,
                                   a.z + b2.z + c2.z + d2.z, a.w + b2.w + c2.w + d2.w);
            ((float4*)g_sumK)[(size_t)bl * 32 + g] = r;
            __half hx = __float2half_rn(r.x), hy = __float2half_rn(r.y);
            __half hz = __float2half_rn(r.z), hw = __float2half_rn(r.w);
            size_t o = (size_t)bl * 64 + g * 2;
            { __half2 t = __halves2half2(hx, hy); ((uint32_t*)g_sKh)[o] = *(uint32_t*)&t; }
            { __half2 t = __halves2half2(hz, hw); ((uint32_t*)g_sKh)[o + 1] = *(uint32_t*)&t; }
            ((uint32_t*)g_sKl)[o] =
                packh2(r.x - __half2float(hx), r.y - __half2float(hy));
            ((uint32_t*)g_sKl)[o + 1] =
                packh2(r.z - __half2float(hz), r.w - __half2float(hw));
        }
    } else {
        if (threadIdx.x >= 32) return;
        int bc = blk - 1024;
        int c = bc & 7, b = bc >> 3;
        int lane = threadIdx.x;
        int cnt = 0;
        for (int l0 = 0; l0 < L_; l0 += 32) {
            int l = l0 + lane;
            int lbl = label[b * L_ + l];
            unsigned m = __ballot_sync(0xffffffffu, lbl == c);
            if (lbl == c) {
                int pos = cnt + __popc(m & ((1u << lane) - 1u));
                g_idx[b][c][pos] = l;
            }
            cnt += __popc(m);
        }
        if (lane == 0) g_cnt[b][c] = cnt;
    }
}

// ===========================================================================
// PTX helpers (family-common, valid on target sm_103)
// ===========================================================================
__device__ __forceinline__ uint32_t smem_u32(const void* p) {
    uint32_t a;
    asm("{ .reg .u64 t; cvta.to.shared.u64 t, %1; cvt.u32.u64 %0, t; }"
        : "=r"(a) : "l"(p));
    return a;
}
__device__ __forceinline__ void cpa16(uint32_t dst, const void* src) {
    asm volatile("cp.async.cg.shared.global [%0], [%1], 16;"
                 :: "r"(dst), "l"(src));
}
__device__ __forceinline__ void ldsm4(uint32_t addr, uint32_t* r) {
    asm volatile("ldmatrix.sync.aligned.m8n8.x4.shared.b16 {%0,%1,%2,%3}, [%4];"
                 : "=r"(r[0]), "=r"(r[1]), "=r"(r[2]), "=r"(r[3]) : "r"(addr));
}
__device__ __forceinline__ void ldsm4t(uint32_t addr, uint32_t* r) {
    asm volatile("ldmatrix.sync.aligned.m8n8.x4.trans.shared.b16 {%0,%1,%2,%3}, [%4];"
                 : "=r"(r[0]), "=r"(r[1]), "=r"(r[2]), "=r"(r[3]) : "r"(addr));
}
__device__ __forceinline__ void mma16816(float* c, const uint32_t* a,
                                         uint32_t b0, uint32_t b1) {
    asm volatile(
        "mma.sync.aligned.m16n8k16.row.col.f32.f16.f16.f32 "
        "{%0,%1,%2,%3}, {%4,%5,%6,%7}, {%8,%9}, {%0,%1,%2,%3};"
        : "+f"(c[0]), "+f"(c[1]), "+f"(c[2]), "+f"(c[3])
        : "r"(a[0]), "r"(a[1]), "r"(a[2]), "r"(a[3]), "r"(b0), "r"(b1));
}
__device__ __forceinline__ void split2(float x0, float x1,
                                       uint32_t& hi, uint32_t& lo) {
    __half h0 = __float2half_rn(x0), h1 = __float2half_rn(x1);
    __half l0 = __float2half_rn(x0 - __half2float(h0));
    __half l1 = __float2half_rn(x1 - __half2float(h1));
    __half2 hp = __halves2half2(h0, h1), lp = __halves2half2(l0, l1);
    hi = *reinterpret_cast<uint32_t*>(&hp);
    lo = *reinterpret_cast<uint32_t*>(&lp);
}
// byte offset in an f16 tile (256B rows), 16B-chunk XOR swizzle
__device__ __forceinline__ uint32_t swz(int row, int col) {
    return (uint32_t)(row * 256) + (uint32_t)((((col >> 3) ^ (row & 7)) & 15) << 4)
         + (uint32_t)((col & 7) << 1);
}
__device__ __forceinline__ uint32_t swz16(int row, int ch) {
    return (uint32_t)(row * 256) + (uint32_t)(((ch ^ (row & 7)) & 15) << 4);
}

// smem layout: P tiles 48 rows; K/V tiles 96 rows (K becomes V).
// fp32 V staging: row r = [KVHI+r*256 | KVLO+r*256]
#define SM_PHI  0
#define SM_PLO  12288
#define SM_KVHI 24576
#define SM_KVLO 49152
#define SM_IDX  73728    /* 96 ints */
#define SM_ORD  74112
#define SM_RED  74240    /* redm[2][48], redl[2][48] */
#define SMEM_TOTAL 75008

// Dead-code-in-practice fallback for nc > 96 (slow, simple, correct).
__device__ __noinline__ void attn_fallback(int b, int c, int k, int nc,
                                           const int* idxs,
                                           const float* query,
                                           const float* value,
                                           float* out) {
    for (int r = threadIdx.x; r < nc; r += blockDim.x) {
        int i = idxs[r];
        const float* q = query + (((size_t)b * L_ + i) * V_ + k) * D_;
        float m = -1e30f;
        for (int jj = 0; jj < nc; jj++) {
            const float* kr = g_sumK + ((size_t)b * L_ + idxs[jj]) * D_;
            float s = 0.f;
            for (int d = 0; d < D_; d++) s += q[d] * kr[d];
            m = fmaxf(m, s * SCALE_);
        }
        float l = 0.f;
        for (int jj = 0; jj < nc; jj++) {
            const float* kr = g_sumK + ((size_t)b * L_ + idxs[jj]) * D_;
            float s = 0.f;
            for (int d = 0; d < D_; d++) s += q[d] * kr[d];
            l += __expf(s * SCALE_ - m);
        }
        for (int d0 = 0; d0 < D_; d0 += 32) {
            float acc[32];
            for (int e = 0; e < 32; e++) acc[e] = 0.f;
            for (int jj = 0; jj < nc; jj++) {
                const float* kr = g_sumK + ((size_t)b * L_ + idxs[jj]) * D_;
                float s = 0.f;
                for (int d = 0; d < D_; d++) s += q[d] * kr[d];
                float p = __expf(s * SCALE_ - m) / l;
                const float* vr = value +
                    (((size_t)b * L_ + idxs[jj]) * V_ + k) * D_ + d0;
                for (int e = 0; e < 32; e++) acc[e] += p * vr[e];
            }
            float* dst = out + (((size_t)b * L_ + i) * V_ + k) * D_ + d0;
            for (int e = 0; e < 32; e++) dst[e] = acc[e];
        }
    }
}

// ===========================================================================
// HMMA clustered attention: CTA = (head, cluster-rank, row-half of 48).
// Q via direct LDG+split; V via cp.async staging; PV = Phi*(Vhi+Vlo).
// ===========================================================================
extern __shared__ char smx[];

__global__ void __launch_bounds__(192, 3)
attn_mma_kernel(const float* __restrict__ query,
                const float* __restrict__ value,
                float* __restrict__ out) {
    const int k = blockIdx.x, cl = blockIdx.y, z = blockIdx.z;
    const int tid = threadIdx.x;
    const int lane = tid & 31;
    const int w = tid >> 5;          // 0..5
    const int half = w & 1;
    const int sid = w >> 1;          // strip 0..2

    // ---- LPT: rank clusters by descending count (deterministic tie-break)
    if (w == 0) {
        int key = -1;
        if (lane < 16) key = (g_cnt[lane >> 3][lane & 7] << 4) | (15 - lane);
        int rank = 0;
#pragma unroll
        for (int j = 0; j < 16; j++) {
            int other = __shfl_sync(0xffffffffu, key, j);
            if (lane < 16 && other > key) rank++;
        }
        if (lane < 16 && rank == cl) *(int*)(smx + SM_ORD) = lane;
    }
    __syncthreads();
    const int ordv = *(int*)(smx + SM_ORD);
    const int b = ordv >> 3, c = ordv & 7;

    const int nc = g_cnt[b][c];
    if (nc == 0) return;
    if (nc > NR_MAX) {
        if (z == 0) attn_fallback(b, c, k, nc, g_idx[b][c], query, value, out);
        return;
    }
    const int rowbase = z * 48;
    int nloc = nc - rowbase;
    if (nloc <= 0) return;
    if (nloc > 48) nloc = 48;

    int* idxs = (int*)(smx + SM_IDX);
    for (int t = tid; t < nc; t += 192) idxs[t] = g_idx[b][c][t];
    __syncthreads();

    const int nr = (nc + 15) & ~15;           // K/V rows, <= 96
    const int npair = nr >> 4;                // <= 6

    const uint32_t sb  = smem_u32(smx);
    const uint32_t phi = sb + SM_PHI, plo = sb + SM_PLO;
    const uint32_t kvh = sb + SM_KVHI, kvl = sb + SM_KVLO;

    // ---- K (pre-split hi/lo) via cp.async ----
    for (int t = tid; t < nr * 16; t += 192) {
        int row = t >> 4, ch = t & 15;
        uint32_t so = swz16(row, ch);
        if (row < nc) {
            size_t kb = (((size_t)b * L_ + idxs[row]) << 8) + (ch << 4);
            cpa16(kvh + so, (const char*)g_sKh + kb);
            cpa16(kvl + so, (const char*)g_sKl + kb);
        } else {
            uint4 zz = make_uint4(0, 0, 0, 0);
            *(uint4*)(smx + SM_KVHI + so) = zz;
            *(uint4*)(smx + SM_KVLO + so) = zz;
        }
    }
    asm volatile("cp.async.commit_group;");

    // ---- Q: direct LDG.128 (one row per warp-inst) -> split -> STS.64 ----
    {
        float4 qv[8];
#pragma unroll
        for (int i = 0; i < 8; i++) {
            int gr = rowbase + w + 6 * i;
            if (gr < nc)
                qv[i] = ((const float4*)query)[
                    ((((size_t)b * L_ + idxs[gr]) * V_ + k) << 5) + lane];
        }
#pragma unroll
        for (int i = 0; i < 8; i++) {
            int lr = w + 6 * i;
            int gr = rowbase + lr;
            uint32_t h0 = 0, l0 = 0, h1 = 0, l1 = 0;
            if (gr < nc) {
                split2(qv[i].x * SCALE_, qv[i].y * SCALE_, h0, l0);
                split2(qv[i].z * SCALE_, qv[i].w * SCALE_, h1, l1);
            }
            uint32_t off = swz(lr, lane * 4);   // cols 4L..4L+3 share a chunk
            *(uint2*)(smx + SM_PHI + off) = make_uint2(h0, h1);
            *(uint2*)(smx + SM_PLO + off) = make_uint2(l0, l1);
        }
    }
    asm volatile("cp.async.wait_group 0;" ::: "memory");
    __syncthreads();

    float* redm = (float*)(smx + SM_RED);     // [2][48]
    float* redl = redm + 96;

    const int g  = lane >> 3;
    const int rA = (lane & 7) + ((g & 1) << 3);
    const int cA = ((g >> 1) & 1) << 3;
    const int rB = (lane & 7) + (((g >> 1) & 1) << 3);
    const int cB = (g & 1) << 3;
    const int colb = (lane & 3) << 1;
    const int qr = lane >> 2;

    const int lr0 = sid * 16;
    const bool active = lr0 < nloc;
    const int r1 = lr0 + qr, r2 = r1 + 8;     // local P rows

    // ================= S = Q * Ksum^T (full 3-term) ====================
    float cS[6][4];
#pragma unroll
    for (int n = 0; n < 6; n++)
#pragma unroll
        for (int r = 0; r < 4; r++) cS[n][r] = 0.f;

    if (active) {
#pragma unroll
        for (int s = 0; s < 8; s++) {
            uint32_t ah[4], al[4], bh[3][4], bl[3][4];
            ldsm4(phi + swz(lr0 + rA, s * 16 + cA), ah);
            ldsm4(plo + swz(lr0 + rA, s * 16 + cA), al);
#pragma unroll
            for (int u = 0; u < 3; u++) {
                int ti = half + 2 * u;
                if (ti < npair) {
                    ldsm4(kvh + swz(16 * ti + rB, s * 16 + cB), bh[u]);
                    ldsm4(kvl + swz(16 * ti + rB, s * 16 + cB), bl[u]);
                }
            }
#pragma unroll
            for (int u = 0; u < 3; u++)
                if (half + 2 * u < npair) {
                    mma16816(cS[2 * u],     ah, bh[u][0], bh[u][1]);
                    mma16816(cS[2 * u + 1], ah, bh[u][2], bh[u][3]);
                }
#pragma unroll
            for (int u = 0; u < 3; u++)
                if (half + 2 * u < npair) {
                    mma16816(cS[2 * u],     ah, bl[u][0], bl[u][1]);
                    mma16816(cS[2 * u + 1], ah, bl[u][2], bl[u][3]);
                }
#pragma unroll
            for (int u = 0; u < 3; u++)
                if (half + 2 * u < npair) {
                    mma16816(cS[2 * u],     al, bh[u][0], bh[u][1]);
                    mma16816(cS[2 * u + 1], al, bh[u][2], bh[u][3]);
                }
        }

        float m0 = -1e30f, m1 = -1e30f;
#pragma unroll
        for (int u = 0; u < 3; u++) {
            int ti = half + 2 * u;
            if (ti < npair) {
#pragma unroll
                for (int sub = 0; sub < 2; sub++) {
                    int n = 2 * u + sub;
                    int c0 = ti * 16 + sub * 8 + colb;
                    if (c0 < nc)     { m0 = fmaxf(m0, cS[n][0]); m1 = fmaxf(m1, cS[n][2]); }
                    if (c0 + 1 < nc) { m0 = fmaxf(m0, cS[n][1]); m1 = fmaxf(m1, cS[n][3]); }
                }
            }
        }
        m0 = fmaxf(m0, __shfl_xor_sync(0xffffffffu, m0, 1));
        m0 = fmaxf(m0, __shfl_xor_sync(0xffffffffu, m0, 2));
        m1 = fmaxf(m1, __shfl_xor_sync(0xffffffffu, m1, 1));
        m1 = fmaxf(m1, __shfl_xor_sync(0xffffffffu, m1, 2));
        if ((lane & 3) == 0) {
            redm[half * 48 + r1] = m0;
            redm[half * 48 + r2] = m1;
        }
    }
    __syncthreads();   // all K ldsm done + partial maxes visible

    // ---- early raw-fp32 V issue into KV staging (K dead) -----------------
    for (int t = tid; t < nr * 32; t += 192) {
        int row = t >> 5, ch = t & 31;
        if (row < nc) {
            uint32_t dst = ((ch & 16) ? kvl : kvh) + row * 256 + (ch & 15) * 16;
            size_t vb2 = ((((size_t)b * L_ + idxs[row]) * V_ + k) << 9) + (ch << 4);
            cpa16(dst, (const char*)value + vb2);
        }
    }
    asm volatile("cp.async.commit_group;");

    // ---- softmax: exp, P (hi only) -> smem, partial l --------------------
    if (active) {
        float mt0 = fmaxf(redm[r1], redm[48 + r1]);
        float mt1 = fmaxf(redm[r2], redm[48 + r2]);
        float l0 = 0.f, l1 = 0.f;
#pragma unroll
        for (int u = 0; u < 3; u++) {
            int ti = half + 2 * u;
            if (ti < npair) {
#pragma unroll
                for (int sub = 0; sub < 2; sub++) {
                    int n = 2 * u + sub;
                    int c0 = ti * 16 + sub * 8 + colb;
                    float p0 = (c0     < nc) ? __expf(cS[n][0] - mt0) : 0.f;
                    float p1 = (c0 + 1 < nc) ? __expf(cS[n][1] - mt0) : 0.f;
                    float p2 = (c0     < nc) ? __expf(cS[n][2] - mt1) : 0.f;
                    float p3 = (c0 + 1 < nc) ? __expf(cS[n][3] - mt1) : 0.f;
                    l0 += p0 + p1; l1 += p2 + p3;
                    *(uint32_t*)(smx + SM_PHI + swz(r1, c0)) = packh2(p0, p1);
                    *(uint32_t*)(smx + SM_PHI + swz(r2, c0)) = packh2(p2, p3);
                }
            }
        }
        l0 += __shfl_xor_sync(0xffffffffu, l0, 1);
        l0 += __shfl_xor_sync(0xffffffffu, l0, 2);
        l1 += __shfl_xor_sync(0xffffffffu, l1, 1);
        l1 += __shfl_xor_sync(0xffffffffu, l1, 2);
        if ((lane & 3) == 0) {
            redl[half * 48 + r1] = l0;
            redl[half * 48 + r2] = l1;
        }
    }
    asm volatile("cp.async.wait_group 0;" ::: "memory");
    __syncthreads();   // V staging + P tiles + partial l complete

    // ---- convert V: two 48-row passes, reg-buffered (disjoint regions) ---
    {
#pragma unroll 1
        for (int pass = 0; pass < 2; pass++) {
            if (pass == 1 && nr <= 48) break;
            float2 vb[16];
#pragma unroll
            for (int i = 0; i < 16; i++) {
                int f = i * 192 + tid;
                int row = pass * 48 + (f >> 6), bo = (f & 63) * 8;
                int off = ((bo & 256) ? SM_KVLO : SM_KVHI) + row * 256 + (bo & 255);
                vb[i] = *(const float2*)(smx + off);
            }
            __syncthreads();
#pragma unroll
            for (int i = 0; i < 16; i++) {
                int f = i * 192 + tid;
                int row = pass * 48 + (f >> 6), col = (f & 63) * 2;
                uint32_t hi = 0, lo = 0;
                if (row < nc) split2(vb[i].x, vb[i].y, hi, lo);
                *(uint32_t*)(smx + SM_KVHI + swz(row, col)) = hi;
                *(uint32_t*)(smx + SM_KVLO + swz(row, col)) = lo;
            }
            __syncthreads();
        }
    }

    // ================= O = Phi * (Vhi + Vlo)  (d-range = half*64..+63) =====
    if (active) {
        float o[8][4];
#pragma unroll
        for (int n = 0; n < 8; n++)
#pragma unroll
            for (int r = 0; r < 4; r++) o[n][r] = 0.f;

#pragma unroll
        for (int kt = 0; kt < 6; kt++) {
            if (kt < npair) {
                uint32_t ph[4], vh[4][4], vl[4][4];
                ldsm4(phi + swz(lr0 + rA, kt * 16 + cA), ph);
#pragma unroll
                for (int dq = 0; dq < 4; dq++) {
                    int dp = half * 4 + dq;
                    ldsm4t(kvh + swz(16 * kt + rA, 16 * dp + cA), vh[dq]);
                    ldsm4t(kvl + swz(16 * kt + rA, 16 * dp + cA), vl[dq]);
                }
#pragma unroll
                for (int dq = 0; dq < 4; dq++) {
                    mma16816(o[2 * dq],     ph, vh[dq][0], vh[dq][1]);
                    mma16816(o[2 * dq + 1], ph, vh[dq][2], vh[dq][3]);
                }
#pragma unroll
                for (int dq = 0; dq < 4; dq++) {
                    mma16816(o[2 * dq],     ph, vl[dq][0], vl[dq][1]);
                    mma16816(o[2 * dq + 1], ph, vl[dq][2], vl[dq][3]);
                }
            }
        }

        // ---- epilogue
        float lt0 = redl[r1] + redl[48 + r1];
        float lt1 = redl[r2] + redl[48 + r2];
        float i0 = 1.f / lt0, i1 = 1.f / lt1;
        int gr1 = rowbase + r1, gr2 = rowbase + r2;
        float* d1 = (gr1 < nc)
            ? out + (((size_t)b * L_ + idxs[gr1]) * V_ + k) * D_ : nullptr;
        float* d2 = (gr2 < nc)
            ? out + (((size_t)b * L_ + idxs[gr2]) * V_ + k) * D_ : nullptr;
#pragma unroll
        for (int n = 0; n < 8; n++) {
            int col = half * 64 + (n >> 1) * 16 + (n & 1) * 8 + colb;
            if (d1) *(float2*)(d1 + col) = make_float2(o[n][0] * i0, o[n][1] * i0);
            if (d2) *(float2*)(d2 + col) = make_float2(o[n][2] * i1, o[n][3] * i1);
        }
    }
}

extern "C" void kernel_launch(void* const* d_in, const int* in_sizes, int n_in,
                              void* d_out, int out_size) {
    (void)in_sizes; (void)n_in; (void)out_size;
    const float* query = (const float*)d_in[0];
    const float* key   = (const float*)d_in[1];
    const float* value = (const float*)d_in[2];
    const int*   label = (const int*)d_in[3];
    float* out = (float*)d_out;

    prep_kernel<<<1040, 256>>>((const float4*)key, label);
    cudaFuncSetAttribute(attn_mma_kernel,
                         cudaFuncAttributeMaxDynamicSharedMemorySize, SMEM_TOTAL);
    attn_mma_kernel<<<dim3(V_, 16, 2), 192, SMEM_TOTAL>>>(query, value, out);
}

// round 12
// speedup vs baseline: 3.5776x; 1.1120x over previous
#include <cuda_runtime.h>
#include <cuda_fp16.h>
#include <cstdint>

#define B_ 2
#define L_ 512
#define V_ 64
#define D_ 128
#define NC_ 8
#define NR_MAX 96

// ---- static device scratch (no allocations allowed) ----
__device__ float  g_sumK[B_ * L_ * D_];
__device__ __half g_sKh[B_ * L_ * D_];
__device__ __half g_sKl[B_ * L_ * D_];
__device__ int    g_idx[B_][NC_][L_];
__device__ int    g_cnt[B_][NC_];

#define SCALE_ 0.08838834764831845f

__device__ __forceinline__ uint32_t packh2(float a, float b2) {
    __half2 h = __halves2half2(__float2half_rn(a), __float2half_rn(b2));
    return *reinterpret_cast<uint32_t*>(&h);
}

// ===========================================================================
// Prep kernel: blocks [0,1024) sumK (+fp16 hi/lo); [1024,1040) idx lists
// ===========================================================================
__global__ void prep_kernel(const float4* __restrict__ key4,
                            const int* __restrict__ label) {
    __shared__ float4 part[256];
    const int blk = blockIdx.x;

    if (blk < 1024) {
        int bl = blk;
        int g = threadIdx.x & 31, qd = threadIdx.x >> 5;
        const float4* p = key4 + (size_t)bl * (V_ * D_ / 4)
                        + (size_t)(qd * 8) * (D_ / 4) + g;
        float4 s = make_float4(0.f, 0.f, 0.f, 0.f);
#pragma unroll
        for (int vv = 0; vv < 8; vv++) {
            float4 t = p[(size_t)vv * (D_ / 4)];
            s.x += t.x; s.y += t.y; s.z += t.z; s.w += t.w;
        }
        part[threadIdx.x] = s;
        __syncthreads();
        if (qd < 4) {
            float4 a = part[threadIdx.x], b2 = part[threadIdx.x + 128];
            part[threadIdx.x] =
                make_float4(a.x + b2.x, a.y + b2.y, a.z + b2.z, a.w + b2.w);
        }
        __syncthreads();
        if (qd == 0) {
            float4 a = part[g], b2 = part[32 + g], c2 = part[64 + g], d2 = part[96 + g];
            float4 r = make_float4(a.x + b2.x + c2.x + d2.x, a.y + b2.y + c2.y + d2.y,
                                   a.z + b2.z + c2.z + d2.z, a.w + b2.w + c2.w + d2.w);
            ((float4*)g_sumK)[(size_t)bl * 32 + g] = r;
            __half hx = __float2half_rn(r.x), hy = __float2half_rn(r.y);
            __half hz = __float2half_rn(r.z), hw = __float2half_rn(r.w);
            size_t o = (size_t)bl * 64 + g * 2;
            { __half2 t = __halves2half2(hx, hy); ((uint32_t*)g_sKh)[o] = *(uint32_t*)&t; }
            { __half2 t = __halves2half2(hz, hw); ((uint32_t*)g_sKh)[o + 1] = *(uint32_t*)&t; }
            ((uint32_t*)g_sKl)[o] =
                packh2(r.x - __half2float(hx), r.y - __half2float(hy));
            ((uint32_t*)g_sKl)[o + 1] =
                packh2(r.z - __half2float(hz), r.w - __half2float(hw));
        }
    } else {
        if (threadIdx.x >= 32) return;
        int bc = blk - 1024;
        int c = bc & 7, b = bc >> 3;
        int lane = threadIdx.x;
        int cnt = 0;
        for (int l0 = 0; l0 < L_; l0 += 32) {
            int l = l0 + lane;
            int lbl = label[b * L_ + l];
            unsigned m = __ballot_sync(0xffffffffu, lbl == c);
            if (lbl == c) {
                int pos = cnt + __popc(m & ((1u << lane) - 1u));
                g_idx[b][c][pos] = l;
            }
            cnt += __popc(m);
        }
        if (lane == 0) g_cnt[b][c] = cnt;
    }
}

// ===========================================================================
// PTX helpers (family-common, valid on target sm_103)
// ===========================================================================
__device__ __forceinline__ uint32_t smem_u32(const void* p) {
    uint32_t a;
    asm("{ .reg .u64 t; cvta.to.shared.u64 t, %1; cvt.u32.u64 %0, t; }"
        : "=r"(a) : "l"(p));
    return a;
}
__device__ __forceinline__ void cpa16(uint32_t dst, const void* src) {
    asm volatile("cp.async.cg.shared.global [%0], [%1], 16;"
                 :: "r"(dst), "l"(src));
}
__device__ __forceinline__ void ldsm4(uint32_t addr, uint32_t* r) {
    asm volatile("ldmatrix.sync.aligned.m8n8.x4.shared.b16 {%0,%1,%2,%3}, [%4];"
                 : "=r"(r[0]), "=r"(r[1]), "=r"(r[2]), "=r"(r[3]) : "r"(addr));
}
__device__ __forceinline__ void ldsm4t(uint32_t addr, uint32_t* r) {
    asm volatile("ldmatrix.sync.aligned.m8n8.x4.trans.shared.b16 {%0,%1,%2,%3}, [%4];"
                 : "=r"(r[0]), "=r"(r[1]), "=r"(r[2]), "=r"(r[3]) : "r"(addr));
}
__device__ __forceinline__ void mma16816(float* c, const uint32_t* a,
                                         uint32_t b0, uint32_t b1) {
    asm volatile(
        "mma.sync.aligned.m16n8k16.row.col.f32.f16.f16.f32 "
        "{%0,%1,%2,%3}, {%4,%5,%6,%7}, {%8,%9}, {%0,%1,%2,%3};"
        : "+f"(c[0]), "+f"(c[1]), "+f"(c[2]), "+f"(c[3])
        : "r"(a[0]), "r"(a[1]), "r"(a[2]), "r"(a[3]), "r"(b0), "r"(b1));
}
__device__ __forceinline__ void split2(float x0, float x1,
                                       uint32_t& hi, uint32_t& lo) {
    __half h0 = __float2half_rn(x0), h1 = __float2half_rn(x1);
    __half l0 = __float2half_rn(x0 - __half2float(h0));
    __half l1 = __float2half_rn(x1 - __half2float(h1));
    __half2 hp = __halves2half2(h0, h1), lp = __halves2half2(l0, l1);
    hi = *reinterpret_cast<uint32_t*>(&hp);
    lo = *reinterpret_cast<uint32_t*>(&lp);
}
// byte offset in an f16 tile (256B rows), 16B-chunk XOR swizzle
__device__ __forceinline__ uint32_t swz(int row, int col) {
    return (uint32_t)(row * 256) + (uint32_t)((((col >> 3) ^ (row & 7)) & 15) << 4)
         + (uint32_t)((col & 7) << 1);
}
__device__ __forceinline__ uint32_t swz16(int row, int ch) {
    return (uint32_t)(row * 256) + (uint32_t)(((ch ^ (row & 7)) & 15) << 4);
}

// smem layout: P tiles 48 rows; K hi/lo tiles 96 rows; V (hi-only) over K-hi
#define SM_PHI  0
#define SM_PLO  12288
#define SM_KVHI 24576
#define SM_KLO  49152
#define SM_IDX  73728    /* 96 ints */
#define SM_ORD  74112
#define SM_RED  74240    /* redm[2][48], redl[2][48] */
#define SMEM_TOTAL 75008

// Dead-code-in-practice fallback for nc > 96 (slow, simple, correct).
__device__ __noinline__ void attn_fallback(int b, int c, int k, int nc,
                                           const int* idxs,
                                           const float* query,
                                           const float* value,
                                           float* out) {
    for (int r = threadIdx.x; r < nc; r += blockDim.x) {
        int i = idxs[r];
        const float* q = query + (((size_t)b * L_ + i) * V_ + k) * D_;
        float m = -1e30f;
        for (int jj = 0; jj < nc; jj++) {
            const float* kr = g_sumK + ((size_t)b * L_ + idxs[jj]) * D_;
            float s = 0.f;
            for (int d = 0; d < D_; d++) s += q[d] * kr[d];
            m = fmaxf(m, s * SCALE_);
        }
        float l = 0.f;
        for (int jj = 0; jj < nc; jj++) {
            const float* kr = g_sumK + ((size_t)b * L_ + idxs[jj]) * D_;
            float s = 0.f;
            for (int d = 0; d < D_; d++) s += q[d] * kr[d];
            l += __expf(s * SCALE_ - m);
        }
        for (int d0 = 0; d0 < D_; d0 += 32) {
            float acc[32];
            for (int e = 0; e < 32; e++) acc[e] = 0.f;
            for (int jj = 0; jj < nc; jj++) {
                const float* kr = g_sumK + ((size_t)b * L_ + idxs[jj]) * D_;
                float s = 0.f;
                for (int d = 0; d < D_; d++) s += q[d] * kr[d];
                float p = __expf(s * SCALE_ - m) / l;
                const float* vr = value +
                    (((size_t)b * L_ + idxs[jj]) * V_ + k) * D_ + d0;
                for (int e = 0; e < 32; e++) acc[e] += p * vr[e];
            }
            float* dst = out + (((size_t)b * L_ + i) * V_ + k) * D_ + d0;
            for (int e = 0; e < 32; e++) dst[e] = acc[e];
        }
    }
}

// ===========================================================================
// HMMA clustered attention: CTA = (head, cluster-rank, row-half of 48).
// Q,V direct LDG+split; K pre-split via cp.async; PV = Phi*Vhi only.
// ===========================================================================
extern __shared__ char smx[];

__global__ void __launch_bounds__(192, 3)
attn_mma_kernel(const float* __restrict__ query,
                const float* __restrict__ value,
                float* __restrict__ out) {
    const int k = blockIdx.x, cl = blockIdx.y, z = blockIdx.z;
    const int tid = threadIdx.x;
    const int lane = tid & 31;
    const int w = tid >> 5;          // 0..5
    const int half = w & 1;
    const int sid = w >> 1;          // strip 0..2

    // ---- LPT: rank clusters by descending count (deterministic tie-break)
    if (w == 0) {
        int key = -1;
        if (lane < 16) key = (g_cnt[lane >> 3][lane & 7] << 4) | (15 - lane);
        int rank = 0;
#pragma unroll
        for (int j = 0; j < 16; j++) {
            int other = __shfl_sync(0xffffffffu, key, j);
            if (lane < 16 && other > key) rank++;
        }
        if (lane < 16 && rank == cl) *(int*)(smx + SM_ORD) = lane;
    }
    __syncthreads();
    const int ordv = *(int*)(smx + SM_ORD);
    const int b = ordv >> 3, c = ordv & 7;

    const int nc = g_cnt[b][c];
    if (nc == 0) return;
    if (nc > NR_MAX) {
        if (z == 0) attn_fallback(b, c, k, nc, g_idx[b][c], query, value, out);
        return;
    }
    const int rowbase = z * 48;
    int nloc = nc - rowbase;
    if (nloc <= 0) return;
    if (nloc > 48) nloc = 48;

    int* idxs = (int*)(smx + SM_IDX);
    for (int t = tid; t < nc; t += 192) idxs[t] = g_idx[b][c][t];
    __syncthreads();

    const int nr = (nc + 15) & ~15;           // K/V rows, <= 96
    const int npair = nr >> 4;                // <= 6

    const uint32_t sb  = smem_u32(smx);
    const uint32_t phi = sb + SM_PHI, plo = sb + SM_PLO;
    const uint32_t kvh = sb + SM_KVHI, klo = sb + SM_KLO;

    // ---- K (pre-split hi/lo) via cp.async ----
    for (int t = tid; t < nr * 16; t += 192) {
        int row = t >> 4, ch = t & 15;
        uint32_t so = swz16(row, ch);
        if (row < nc) {
            size_t kb = (((size_t)b * L_ + idxs[row]) << 8) + (ch << 4);
            cpa16(kvh + so, (const char*)g_sKh + kb);
            cpa16(klo + so, (const char*)g_sKl + kb);
        } else {
            uint4 zz = make_uint4(0, 0, 0, 0);
            *(uint4*)(smx + SM_KVHI + so) = zz;
            *(uint4*)(smx + SM_KLO + so) = zz;
        }
    }
    asm volatile("cp.async.commit_group;");

    // ---- Q: direct LDG.128 (one row per warp-inst) -> split -> STS.64 ----
    {
        float4 qv[8];
#pragma unroll
        for (int i = 0; i < 8; i++) {
            int gr = rowbase + w + 6 * i;
            if (gr < nc)
                qv[i] = ((const float4*)query)[
                    ((((size_t)b * L_ + idxs[gr]) * V_ + k) << 5) + lane];
        }
#pragma unroll
        for (int i = 0; i < 8; i++) {
            int lr = w + 6 * i;
            int gr = rowbase + lr;
            uint32_t h0 = 0, l0 = 0, h1 = 0, l1 = 0;
            if (gr < nc) {
                split2(qv[i].x * SCALE_, qv[i].y * SCALE_, h0, l0);
                split2(qv[i].z * SCALE_, qv[i].w * SCALE_, h1, l1);
            }
            uint32_t off = swz(lr, lane * 4);   // cols 4L..4L+3 share a chunk
            *(uint2*)(smx + SM_PHI + off) = make_uint2(h0, h1);
            *(uint2*)(smx + SM_PLO + off) = make_uint2(l0, l1);
        }
    }
    asm volatile("cp.async.wait_group 0;" ::: "memory");
    __syncthreads();

    float* redm = (float*)(smx + SM_RED);     // [2][48]
    float* redl = redm + 96;

    const int g  = lane >> 3;
    const int rA = (lane & 7) + ((g & 1) << 3);
    const int cA = ((g >> 1) & 1) << 3;
    const int rB = (lane & 7) + (((g >> 1) & 1) << 3);
    const int cB = (g & 1) << 3;
    const int colb = (lane & 3) << 1;
    const int qr = lane >> 2;

    const int lr0 = sid * 16;
    const bool active = lr0 < nloc;
    const int r1 = lr0 + qr, r2 = r1 + 8;     // local P rows

    // ================= S = Q * Ksum^T (full 3-term) ====================
    float cS[6][4];
#pragma unroll
    for (int n = 0; n < 6; n++)
#pragma unroll
        for (int r = 0; r < 4; r++) cS[n][r] = 0.f;

    if (active) {
#pragma unroll
        for (int s = 0; s < 8; s++) {
            uint32_t ah[4], al[4], bh[3][4], bl[3][4];
            ldsm4(phi + swz(lr0 + rA, s * 16 + cA), ah);
            ldsm4(plo + swz(lr0 + rA, s * 16 + cA), al);
#pragma unroll
            for (int u = 0; u < 3; u++) {
                int ti = half + 2 * u;
                if (ti < npair) {
                    ldsm4(kvh + swz(16 * ti + rB, s * 16 + cB), bh[u]);
                    ldsm4(klo + swz(16 * ti + rB, s * 16 + cB), bl[u]);
                }
            }
#pragma unroll
            for (int u = 0; u < 3; u++)
                if (half + 2 * u < npair) {
                    mma16816(cS[2 * u],     ah, bh[u][0], bh[u][1]);
                    mma16816(cS[2 * u + 1], ah, bh[u][2], bh[u][3]);
                }
#pragma unroll
            for (int u = 0; u < 3; u++)
                if (half + 2 * u < npair) {
                    mma16816(cS[2 * u],     ah, bl[u][0], bl[u][1]);
                    mma16816(cS[2 * u + 1], ah, bl[u][2], bl[u][3]);
                }
#pragma unroll
            for (int u = 0; u < 3; u++)
                if (half + 2 * u < npair) {
                    mma16816(cS[2 * u],     al, bh[u][0], bh[u][1]);
                    mma16816(cS[2 * u + 1], al, bh[u][2], bh[u][3]);
                }
        }

        float m0 = -1e30f, m1 = -1e30f;
#pragma unroll
        for (int u = 0; u < 3; u++) {
            int ti = half + 2 * u;
            if (ti < npair) {
#pragma unroll
                for (int sub = 0; sub < 2; sub++) {
                    int n = 2 * u + sub;
                    int c0 = ti * 16 + sub * 8 + colb;
                    if (c0 < nc)     { m0 = fmaxf(m0, cS[n][0]); m1 = fmaxf(m1, cS[n][2]); }
                    if (c0 + 1 < nc) { m0 = fmaxf(m0, cS[n][1]); m1 = fmaxf(m1, cS[n][3]); }
                }
            }
        }
        m0 = fmaxf(m0, __shfl_xor_sync(0xffffffffu, m0, 1));
        m0 = fmaxf(m0, __shfl_xor_sync(0xffffffffu, m0, 2));
        m1 = fmaxf(m1, __shfl_xor_sync(0xffffffffu, m1, 1));
        m1 = fmaxf(m1, __shfl_xor_sync(0xffffffffu, m1, 2));
        if ((lane & 3) == 0) {
            redm[half * 48 + r1] = m0;
            redm[half * 48 + r2] = m1;
        }
    }
    __syncthreads();   // all K ldsm done (K tiles dead) + partial maxes visible

    // ---- V batch A: direct LDG of rows [0,48) (latency hidden by softmax)
    float4 va[8];
#pragma unroll
    for (int i = 0; i < 8; i++) {
        int row = w + 6 * i;              // 0..47
        if (row < nc)
            va[i] = ((const float4*)value)[
                ((((size_t)b * L_ + idxs[row]) * V_ + k) << 5) + lane];
    }

    // ---- softmax: exp, P (hi only) -> smem, partial l --------------------
    if (active) {
        float mt0 = fmaxf(redm[r1], redm[48 + r1]);
        float mt1 = fmaxf(redm[r2], redm[48 + r2]);
        float l0 = 0.f, l1 = 0.f;
#pragma unroll
        for (int u = 0; u < 3; u++) {
            int ti = half + 2 * u;
            if (ti < npair) {
#pragma unroll
                for (int sub = 0; sub < 2; sub++) {
                    int n = 2 * u + sub;
                    int c0 = ti * 16 + sub * 8 + colb;
                    float p0 = (c0     < nc) ? __expf(cS[n][0] - mt0) : 0.f;
                    float p1 = (c0 + 1 < nc) ? __expf(cS[n][1] - mt0) : 0.f;
                    float p2 = (c0     < nc) ? __expf(cS[n][2] - mt1) : 0.f;
                    float p3 = (c0 + 1 < nc) ? __expf(cS[n][3] - mt1) : 0.f;
                    l0 += p0 + p1; l1 += p2 + p3;
                    *(uint32_t*)(smx + SM_PHI + swz(r1, c0)) = packh2(p0, p1);
                    *(uint32_t*)(smx + SM_PHI + swz(r2, c0)) = packh2(p2, p3);
                }
            }
        }
        l0 += __shfl_xor_sync(0xffffffffu, l0, 1);
        l0 += __shfl_xor_sync(0xffffffffu, l0, 2);
        l1 += __shfl_xor_sync(0xffffffffu, l1, 1);
        l1 += __shfl_xor_sync(0xffffffffu, l1, 2);
        if ((lane & 3) == 0) {
            redl[half * 48 + r1] = l0;
            redl[half * 48 + r2] = l1;
        }
    }

    // ---- V batch B LDG (rows [48,96)), then store both batches as fp16 hi
    {
        float4 vbB[8];
#pragma unroll
        for (int i = 0; i < 8; i++) {
            int row = 48 + w + 6 * i;     // 48..95
            if (row < nc)
                vbB[i] = ((const float4*)value)[
                    ((((size_t)b * L_ + idxs[row]) * V_ + k) << 5) + lane];
        }
#pragma unroll
        for (int i = 0; i < 8; i++) {
            int row = w + 6 * i;
            uint32_t h0 = 0, h1 = 0;
            if (row < nc) {
                h0 = packh2(va[i].x, va[i].y);
                h1 = packh2(va[i].z, va[i].w);
            }
            if (row < nr)
                *(uint2*)(smx + SM_KVHI + swz(row, lane * 4)) = make_uint2(h0, h1);
        }
#pragma unroll
        for (int i = 0; i < 8; i++) {
            int row = 48 + w + 6 * i;
            uint32_t h0 = 0, h1 = 0;
            if (row < nc) {
                h0 = packh2(vbB[i].x, vbB[i].y);
                h1 = packh2(vbB[i].z, vbB[i].w);
            }
            if (row < nr)
                *(uint2*)(smx + SM_KVHI + swz(row, lane * 4)) = make_uint2(h0, h1);
        }
    }
    __syncthreads();   // V tile + P tiles + partial l complete

    // ================= O = Phi * Vhi  (d-range = half*64..+63) =============
    if (active) {
        float o[8][4];
#pragma unroll
        for (int n = 0; n < 8; n++)
#pragma unroll
            for (int r = 0; r < 4; r++) o[n][r] = 0.f;

#pragma unroll
        for (int kt = 0; kt < 6; kt++) {
            if (kt < npair) {
                uint32_t ph[4], vh[4][4];
                ldsm4(phi + swz(lr0 + rA, kt * 16 + cA), ph);
#pragma unroll
                for (int dq = 0; dq < 4; dq++) {
                    int dp = half * 4 + dq;
                    ldsm4t(kvh + swz(16 * kt + rA, 16 * dp + cA), vh[dq]);
                }
#pragma unroll
                for (int dq = 0; dq < 4; dq++) {
                    mma16816(o[2 * dq],     ph, vh[dq][0], vh[dq][1]);
                    mma16816(o[2 * dq + 1], ph, vh[dq][2], vh[dq][3]);
                }
            }
        }

        // ---- epilogue
        float lt0 = redl[r1] + redl[48 + r1];
        float lt1 = redl[r2] + redl[48 + r2];
        float i0 = 1.f / lt0, i1 = 1.f / lt1;
        int gr1 = rowbase + r1, gr2 = rowbase + r2;
        float* d1 = (gr1 < nc)
            ? out + (((size_t)b * L_ + idxs[gr1]) * V_ + k) * D_ : nullptr;
        float* d2 = (gr2 < nc)
            ? out + (((size_t)b * L_ + idxs[gr2]) * V_ + k) * D_ : nullptr;
#pragma unroll
        for (int n = 0; n < 8; n++) {
            int col = half * 64 + (n >> 1) * 16 + (n & 1) * 8 + colb;
            if (d1) *(float2*)(d1 + col) = make_float2(o[n][0] * i0, o[n][1] * i0);
            if (d2) *(float2*)(d2 + col) = make_float2(o[n][2] * i1, o[n][3] * i1);
        }
    }
}

extern "C" void kernel_launch(void* const* d_in, const int* in_sizes, int n_in,
                              void* d_out, int out_size) {
    (void)in_sizes; (void)n_in; (void)out_size;
    const float* query = (const float*)d_in[0];
    const float* key   = (const float*)d_in[1];
    const float* value = (const float*)d_in[2];
    const int*   label = (const int*)d_in[3];
    float* out = (float*)d_out;

    prep_kernel<<<1040, 256>>>((const float4*)key, label);
    cudaFuncSetAttribute(attn_mma_kernel,
                         cudaFuncAttributeMaxDynamicSharedMemorySize, SMEM_TOTAL);
    attn_mma_kernel<<<dim3(V_, 16, 2), 192, SMEM_TOTAL>>>(query, value, out);
}